// round 1
// baseline (speedup 1.0000x reference)
#include <cuda_runtime.h>
#include <math.h>

#define B_    8
#define C_    192
#define HEADS_ 8
#define HD_   24
#define HW_   128
#define NPIX_ 16384
#define C3_   576

// ---------------- scratch (static __device__ — no allocations) ----------------
__device__ float g_qkv [(size_t)B_ * C3_ * NPIX_];   // after 1x1 conv
__device__ float g_qkv2[(size_t)B_ * C3_ * NPIX_];   // after depthwise 3x3
__device__ float g_obuf[(size_t)B_ * C_  * NPIX_];   // gated attention output
__device__ float g_gates[(size_t)B_ * HEADS_ * NPIX_]; // gates * topk
__device__ float g_rnorm[B_ * 2 * C_];               // 1/||row|| for q (0..191) and k (192..383)
__device__ float g_attn [B_ * HEADS_ * HD_ * HD_];

// ---------------- router: logits -> softmax -> top2 -> renorm gates ----------------
__global__ void router_kernel(const float* __restrict__ x,
                              const float* __restrict__ rw_main,
                              const float* __restrict__ rw_aux,
                              const int*   __restrict__ task_id,
                              float* __restrict__ gates) {
    int n = blockIdx.x * blockDim.x + threadIdx.x;   // pixel
    int b = blockIdx.y;
    const float* rw = (task_id[0] == 0) ? rw_main : rw_aux;

    __shared__ float w[HEADS_ * C_];
    for (int i = threadIdx.x; i < HEADS_ * C_; i += blockDim.x) w[i] = rw[i];
    __syncthreads();

    const float* xb = x + (size_t)b * C_ * NPIX_ + n;
    float logit[HEADS_];
#pragma unroll
    for (int h = 0; h < HEADS_; h++) logit[h] = 0.f;
    for (int c = 0; c < C_; c++) {
        float xv = xb[(size_t)c * NPIX_];
#pragma unroll
        for (int h = 0; h < HEADS_; h++) logit[h] += xv * w[h * C_ + c];
    }
    // softmax over heads
    float mx = logit[0];
#pragma unroll
    for (int h = 1; h < HEADS_; h++) mx = fmaxf(mx, logit[h]);
    float p[HEADS_]; float s = 0.f;
#pragma unroll
    for (int h = 0; h < HEADS_; h++) { p[h] = expf(logit[h] - mx); s += p[h]; }
    float inv = 1.f / s;
#pragma unroll
    for (int h = 0; h < HEADS_; h++) p[h] *= inv;
    // top-2 (first occurrence wins on ties, matching lax.top_k)
    int h1 = 0;
#pragma unroll
    for (int h = 1; h < HEADS_; h++) if (p[h] > p[h1]) h1 = h;
    int h2 = -1;
#pragma unroll
    for (int h = 0; h < HEADS_; h++) if (h != h1 && (h2 < 0 || p[h] > p[h2])) h2 = h;
    float denom = fmaxf(p[h1] + p[h2], 1.1920929e-07f);
    float gscale = 2.0f / denom;   // fold topk=2 in here
#pragma unroll
    for (int h = 0; h < HEADS_; h++) {
        float g = (h == h1) ? p[h1] * gscale : ((h == h2) ? p[h2] * gscale : 0.f);
        gates[((size_t)b * HEADS_ + h) * NPIX_ + n] = g;
    }
}

// ---------------- tiled SGEMM: Y[b] = W(MxK) * X[b](KxN), row-major ----------------
template<int BM, int BN, int BK, int TM, int TN>
__global__ void gemm_wx(const float* __restrict__ W, const float* __restrict__ X,
                        float* __restrict__ Y, int M, int K, int N) {
    int b = blockIdx.z;
    X += (size_t)b * K * N;
    Y += (size_t)b * M * N;

    __shared__ float Ws[BK][BM];
    __shared__ float Xs[BK][BN];

    const int THREADS = (BM / TM) * (BN / TN);
    int t  = threadIdx.x;
    int tx = t % (BN / TN);
    int ty = t / (BN / TN);
    int row0 = blockIdx.y * BM;
    int col0 = blockIdx.x * BN;

    float acc[TM][TN];
#pragma unroll
    for (int i = 0; i < TM; i++)
#pragma unroll
        for (int j = 0; j < TN; j++) acc[i][j] = 0.f;

    for (int k0 = 0; k0 < K; k0 += BK) {
        for (int i = t; i < BM * BK; i += THREADS) {
            int r = i / BK, kk = i % BK;
            Ws[kk][r] = W[(size_t)(row0 + r) * K + k0 + kk];
        }
        for (int i = t; i < BK * BN; i += THREADS) {
            int kk = i / BN, cc = i % BN;
            Xs[kk][cc] = X[(size_t)(k0 + kk) * N + col0 + cc];
        }
        __syncthreads();
#pragma unroll
        for (int kk = 0; kk < BK; kk++) {
            float wv[TM], xv[TN];
#pragma unroll
            for (int i = 0; i < TM; i++) wv[i] = Ws[kk][ty * TM + i];
#pragma unroll
            for (int j = 0; j < TN; j++) xv[j] = Xs[kk][tx * TN + j];
#pragma unroll
            for (int i = 0; i < TM; i++)
#pragma unroll
                for (int j = 0; j < TN; j++) acc[i][j] += wv[i] * xv[j];
        }
        __syncthreads();
    }
#pragma unroll
    for (int i = 0; i < TM; i++)
#pragma unroll
        for (int j = 0; j < TN; j++)
            Y[(size_t)(row0 + ty * TM + i) * N + col0 + tx * TN + j] = acc[i][j];
}

// ---------------- depthwise 3x3, zero pad ----------------
__global__ void dwconv_kernel(const float* __restrict__ in,
                              const float* __restrict__ wgt, // [576,9]
                              float* __restrict__ out) {
    int idx = blockIdx.x * blockDim.x + threadIdx.x;  // pixel 0..16383
    int ch  = blockIdx.y;
    int b   = blockIdx.z;
    int hh = idx >> 7, ww = idx & 127;
    const float* src = in + ((size_t)b * C3_ + ch) * NPIX_;
    const float* kw  = wgt + ch * 9;
    float acc = 0.f;
#pragma unroll
    for (int dy = -1; dy <= 1; dy++) {
        int y = hh + dy;
        if (y < 0 || y >= HW_) continue;
#pragma unroll
        for (int dx = -1; dx <= 1; dx++) {
            int xw = ww + dx;
            if (xw < 0 || xw >= HW_) continue;
            acc += src[y * HW_ + xw] * kw[(dy + 1) * 3 + (dx + 1)];
        }
    }
    out[((size_t)b * C3_ + ch) * NPIX_ + idx] = acc;
}

// ---------------- 1/L2-norm of each q,k row (over N) ----------------
__global__ void norm_kernel(const float* __restrict__ qkv2, float* __restrict__ rnorm) {
    int r = blockIdx.x;              // 0 .. B*384-1
    int b = r / (2 * C_), ch = r % (2 * C_);   // ch: q in [0,192), k in [192,384)
    const float* src = qkv2 + ((size_t)b * C3_ + ch) * NPIX_;
    float s = 0.f;
    for (int i = threadIdx.x; i < NPIX_; i += blockDim.x) { float v = src[i]; s += v * v; }
    __shared__ float red[256];
    red[threadIdx.x] = s;
    __syncthreads();
    for (int o = 128; o > 0; o >>= 1) {
        if (threadIdx.x < o) red[threadIdx.x] += red[threadIdx.x + o];
        __syncthreads();
    }
    if (threadIdx.x == 0) rnorm[r] = 1.f / fmaxf(sqrtf(red[0]), 1e-12f);
}

// ---------------- Gram (q k^T over N) + scale + row softmax ----------------
__global__ void gram_softmax_kernel(const float* __restrict__ qkv2,
                                    const float* __restrict__ rnorm,
                                    float* __restrict__ attn) {
    int h = blockIdx.x, b = blockIdx.y;
    int t = threadIdx.x;             // 0..575
    int c = t / HD_, d = t % HD_;
    const int CH = 128;
    __shared__ float qs[HD_][CH + 1];
    __shared__ float ks[HD_][CH + 1];
    const float* qb = qkv2 + ((size_t)b * C3_ + h * HD_) * NPIX_;
    const float* kb = qkv2 + ((size_t)b * C3_ + C_ + h * HD_) * NPIX_;
    float acc = 0.f;
    for (int n0 = 0; n0 < NPIX_; n0 += CH) {
        for (int i = t; i < HD_ * CH; i += 576) {
            int cc = i / CH, nn = i % CH;
            qs[cc][nn] = qb[(size_t)cc * NPIX_ + n0 + nn];
            ks[cc][nn] = kb[(size_t)cc * NPIX_ + n0 + nn];
        }
        __syncthreads();
#pragma unroll 8
        for (int nn = 0; nn < CH; nn++) acc += qs[c][nn] * ks[d][nn];
        __syncthreads();
    }
    float rq = rnorm[b * 2 * C_ + h * HD_ + c];
    float rk = rnorm[b * 2 * C_ + C_ + h * HD_ + d];
    __shared__ float S[HD_][HD_ + 1];
    S[c][d] = acc * rq * rk * 0.20412414523193154f;   // * hd^-0.5
    __syncthreads();
    if (d == 0) {   // one thread per row does the 24-wide softmax
        float m = -1e30f;
        for (int j = 0; j < HD_; j++) m = fmaxf(m, S[c][j]);
        float ss = 0.f;
        for (int j = 0; j < HD_; j++) { float e = expf(S[c][j] - m); S[c][j] = e; ss += e; }
        float inv = 1.f / ss;
        for (int j = 0; j < HD_; j++) S[c][j] *= inv;
    }
    __syncthreads();
    attn[(((size_t)b * HEADS_ + h) * HD_ + c) * HD_ + d] = S[c][d];
}

// ---------------- out = (attn @ v) * gate, per pixel ----------------
__global__ void av_kernel(const float* __restrict__ qkv2,
                          const float* __restrict__ attn,
                          const float* __restrict__ gates,
                          float* __restrict__ o) {
    int n = blockIdx.x * blockDim.x + threadIdx.x;
    int h = blockIdx.y, b = blockIdx.z;
    __shared__ float A[HD_][HD_];
    const float* ab = attn + ((size_t)b * HEADS_ + h) * HD_ * HD_;
    for (int i = threadIdx.x; i < HD_ * HD_; i += blockDim.x) A[i / HD_][i % HD_] = ab[i];
    __syncthreads();
    const float* v = qkv2 + ((size_t)b * C3_ + 2 * C_ + h * HD_) * NPIX_ + n;
    float acc[HD_];
#pragma unroll
    for (int c = 0; c < HD_; c++) acc[c] = 0.f;
#pragma unroll
    for (int d = 0; d < HD_; d++) {
        float vv = v[(size_t)d * NPIX_];
#pragma unroll
        for (int c = 0; c < HD_; c++) acc[c] += A[c][d] * vv;
    }
    float g = gates[((size_t)b * HEADS_ + h) * NPIX_ + n];   // already * topk
    float* ob = o + ((size_t)b * C_ + h * HD_) * NPIX_ + n;
#pragma unroll
    for (int c = 0; c < HD_; c++) ob[(size_t)c * NPIX_] = acc[c] * g;
}

// ---------------- launch ----------------
extern "C" void kernel_launch(void* const* d_in, const int* in_sizes, int n_in,
                              void* d_out, int out_size) {
    const float* x       = (const float*)d_in[0];
    const float* qkv_w   = (const float*)d_in[1];
    const float* dw_w    = (const float*)d_in[2];
    const float* proj_w  = (const float*)d_in[3];
    const float* rw_main = (const float*)d_in[4];
    const float* rw_aux  = (const float*)d_in[5];
    const int*   task_id = (const int*)d_in[6];
    float* out = (float*)d_out;

    float *qkv, *qkv2, *obuf, *gates, *rnorm, *attn;
    cudaGetSymbolAddress((void**)&qkv,   g_qkv);
    cudaGetSymbolAddress((void**)&qkv2,  g_qkv2);
    cudaGetSymbolAddress((void**)&obuf,  g_obuf);
    cudaGetSymbolAddress((void**)&gates, g_gates);
    cudaGetSymbolAddress((void**)&rnorm, g_rnorm);
    cudaGetSymbolAddress((void**)&attn,  g_attn);

    // 1. router gates
    router_kernel<<<dim3(NPIX_ / 256, B_), 256>>>(x, rw_main, rw_aux, task_id, gates);
    // 2. qkv 1x1 conv: [576,192] x [192,N] per batch
    gemm_wx<64, 64, 16, 4, 4><<<dim3(NPIX_ / 64, C3_ / 64, B_), 256>>>(qkv_w, x, qkv, C3_, C_, NPIX_);
    // 3. depthwise 3x3
    dwconv_kernel<<<dim3(NPIX_ / 256, C3_, B_), 256>>>(qkv, dw_w, qkv2);
    // 4. q,k row norms
    norm_kernel<<<B_ * 2 * C_, 256>>>(qkv2, rnorm);
    // 5. Gram + softmax -> attn [B,heads,24,24]
    gram_softmax_kernel<<<dim3(HEADS_, B_), 576>>>(qkv2, rnorm, attn);
    // 6. attn @ v, gated
    av_kernel<<<dim3(NPIX_ / 256, HEADS_, B_), 256>>>(qkv2, attn, gates, obuf);
    // 7. projection 1x1 conv: [192,192] x [192,N] per batch
    gemm_wx<64, 64, 16, 4, 4><<<dim3(NPIX_ / 64, C_ / 64, B_), 256>>>(proj_w, obuf, out, C_, C_, NPIX_);
}

// round 4
// speedup vs baseline: 1.6409x; 1.6409x over previous
#include <cuda_runtime.h>
#include <cuda_bf16.h>
#include <math.h>
#include <stdint.h>

#define B_     8
#define C_     192
#define HEADS_ 8
#define HD_    24
#define HW_    128
#define NPIX_  16384
#define C3_    576
#define K_     192

// GEMM tiling
#define BM_ 128
#define BN_ 128
#define LDS_ 200                 // padded row length in bf16 (400 B, conflict-free ldmatrix)
#define TILE_B_ (BM_ * LDS_ * 2) // 51200 bytes per tile
#define SM_DYN_SZ (4 * TILE_B_)  // 204800

// ---------------- scratch (static __device__ — no allocations) ----------------
__device__ float g_qkv [(size_t)B_ * C3_ * NPIX_];
__device__ float g_qkv2[(size_t)B_ * C3_ * NPIX_];
__device__ float g_gates[(size_t)B_ * HEADS_ * NPIX_];
__device__ float g_rnorm[B_ * 2 * C_];
__device__ float g_attn [B_ * HEADS_ * HD_ * HD_];
__device__ __nv_bfloat16 g_xt_hi[(size_t)B_ * NPIX_ * K_];
__device__ __nv_bfloat16 g_xt_lo[(size_t)B_ * NPIX_ * K_];
__device__ __nv_bfloat16 g_ot_hi[(size_t)B_ * NPIX_ * K_];
__device__ __nv_bfloat16 g_ot_lo[(size_t)B_ * NPIX_ * K_];
__device__ __nv_bfloat16 g_wq_hi[640 * K_];
__device__ __nv_bfloat16 g_wq_lo[640 * K_];
__device__ __nv_bfloat16 g_wp_hi[256 * K_];
__device__ __nv_bfloat16 g_wp_lo[256 * K_];

// ---------------- helpers ----------------
__device__ __forceinline__ uint32_t smem_u32(const void* p) {
    uint32_t a;
    asm("{ .reg .u64 t; cvta.to.shared.u64 t, %1; cvt.u32.u64 %0, t; }" : "=r"(a) : "l"(p));
    return a;
}
__device__ __forceinline__ void ldm_x4(uint32_t& r0, uint32_t& r1, uint32_t& r2, uint32_t& r3, uint32_t a) {
    asm volatile("ldmatrix.sync.aligned.m8n8.x4.shared.b16 {%0,%1,%2,%3}, [%4];"
                 : "=r"(r0), "=r"(r1), "=r"(r2), "=r"(r3) : "r"(a));
}
__device__ __forceinline__ void ldm_x2(uint32_t& r0, uint32_t& r1, uint32_t a) {
    asm volatile("ldmatrix.sync.aligned.m8n8.x2.shared.b16 {%0,%1}, [%2];"
                 : "=r"(r0), "=r"(r1) : "r"(a));
}
__device__ __forceinline__ void mma16816(float* c, uint32_t a0, uint32_t a1, uint32_t a2, uint32_t a3,
                                         uint32_t b0, uint32_t b1) {
    asm volatile("mma.sync.aligned.m16n8k16.row.col.f32.bf16.bf16.f32 "
                 "{%0,%1,%2,%3}, {%4,%5,%6,%7}, {%8,%9}, {%0,%1,%2,%3};"
                 : "+f"(c[0]), "+f"(c[1]), "+f"(c[2]), "+f"(c[3])
                 : "r"(a0), "r"(a1), "r"(a2), "r"(a3), "r"(b0), "r"(b1));
}

// ---------------- split fp32 -> bf16 hi/lo for weights (padded rows zeroed) ----------------
__global__ void split_w_kernel(const float* __restrict__ w, __nv_bfloat16* __restrict__ hi,
                               __nv_bfloat16* __restrict__ lo, int M, int Mpad) {
    int i = blockIdx.x * 256 + threadIdx.x;
    if (i >= Mpad * K_) return;
    float v = (i < M * K_) ? w[i] : 0.f;
    __nv_bfloat16 h = __float2bfloat16(v);
    hi[i] = h;
    lo[i] = __float2bfloat16(v - __bfloat162float(h));
}

// ---------------- transpose + split x: [B,C,N] f32 -> [B,N,C] bf16 hi/lo ----------------
__global__ void split_transpose_x(const float* __restrict__ x,
                                  __nv_bfloat16* __restrict__ hi, __nv_bfloat16* __restrict__ lo) {
    int b = blockIdx.y;
    int n0 = blockIdx.x * 32;
    __shared__ float tile[C_][33];
    int t = threadIdx.x;
    for (int i = t; i < C_ * 32; i += 256) {
        int c = i >> 5, j = i & 31;
        tile[c][j] = x[((size_t)b * C_ + c) * NPIX_ + n0 + j];
    }
    __syncthreads();
    for (int i = t; i < 32 * C_; i += 256) {
        int j = i / C_, c = i - j * C_;
        float v = tile[c][j];
        __nv_bfloat16 h = __float2bfloat16(v);
        size_t o = ((size_t)b * NPIX_ + n0 + j) * K_ + c;
        hi[o] = h;
        lo[o] = __float2bfloat16(v - __bfloat162float(h));
    }
}

// ---------------- HMMA split-bf16 GEMM: Y[b](Mvalid x N) = W(Mpad x 192) * Xt[b]^T ----------------
// A: W [Mpad, 192] bf16 row-major (hi/lo). B: Xt [NPIX, 192] bf16 row-major (hi/lo).
__global__ void __launch_bounds__(256, 1)
gemm_mma(const __nv_bfloat16* __restrict__ Ahi, const __nv_bfloat16* __restrict__ Alo,
         const __nv_bfloat16* __restrict__ Bhi, const __nv_bfloat16* __restrict__ Blo,
         float* __restrict__ Y, int Mvalid) {
    extern __shared__ char dsm[];
    char* sAh = dsm;
    char* sAl = dsm + TILE_B_;
    char* sBh = dsm + 2 * TILE_B_;
    char* sBl = dsm + 3 * TILE_B_;

    int t = threadIdx.x, wid = t >> 5, lane = t & 31;
    int n0 = blockIdx.x * BN_;
    int m0 = blockIdx.y * BM_;
    int b  = blockIdx.z;

    Y += (size_t)b * Mvalid * NPIX_;   // per-batch output slab (R3 bug fix)

    // ---- gmem -> smem (contiguous int4 spans, padded-row dst) ----
    const int4* srcA_hi = (const int4*)(Ahi + (size_t)m0 * K_);
    const int4* srcA_lo = (const int4*)(Alo + (size_t)m0 * K_);
    const int4* srcB_hi = (const int4*)(Bhi + ((size_t)b * NPIX_ + n0) * K_);
    const int4* srcB_lo = (const int4*)(Blo + ((size_t)b * NPIX_ + n0) * K_);
#pragma unroll 4
    for (int i = t; i < 3072; i += 256) {           // 128 rows * 24 chunks
        int r = i / 24, ck = i - r * 24;
        int off = r * 400 + ck * 16;
        *(int4*)(sAh + off) = srcA_hi[i];
        *(int4*)(sAl + off) = srcA_lo[i];
        *(int4*)(sBh + off) = srcB_hi[i];
        *(int4*)(sBl + off) = srcB_lo[i];
    }
    __syncthreads();

    // warp layout: 2 (M) x 4 (N); warp tile 64 x 32
    int wm = wid >> 2, wn = wid & 3;
    int mBase = wm * 64;          // row within tile
    int nBase = wn * 32;

    float acc[4][4][4];           // [mi][ni][4]
#pragma unroll
    for (int mi = 0; mi < 4; mi++)
#pragma unroll
        for (int ni = 0; ni < 4; ni++)
#pragma unroll
            for (int j = 0; j < 4; j++) acc[mi][ni][j] = 0.f;

    // ldmatrix lane addressing
    int aRow = mBase + (lane & 15);           // + mi*16
    int aK   = (lane >> 4) * 8;               // k offset within 16-chunk
    int bRow = nBase + (lane & 7);            // + ni*8 (lanes 0-15 used; 16-31 replicate)
    int bK   = ((lane >> 3) & 1) * 8;

    uint32_t aOffBase = (uint32_t)(aRow * 400 + aK * 2);
    uint32_t bOffBase = (uint32_t)(bRow * 400 + bK * 2);
    uint32_t uAh = smem_u32(sAh), uAl = smem_u32(sAl);
    uint32_t uBh = smem_u32(sBh), uBl = smem_u32(sBl);

#pragma unroll
    for (int kc = 0; kc < 12; kc++) {
        uint32_t kByte = kc * 32;             // 16 bf16
        uint32_t ah[4][4], al[4][4], bh[4][2], bl[4][2];
#pragma unroll
        for (int mi = 0; mi < 4; mi++) {
            uint32_t o = aOffBase + mi * (16 * 400) + kByte;
            ldm_x4(ah[mi][0], ah[mi][1], ah[mi][2], ah[mi][3], uAh + o);
            ldm_x4(al[mi][0], al[mi][1], al[mi][2], al[mi][3], uAl + o);
        }
#pragma unroll
        for (int ni = 0; ni < 4; ni++) {
            uint32_t o = bOffBase + ni * (8 * 400) + kByte;
            ldm_x2(bh[ni][0], bh[ni][1], uBh + o);
            ldm_x2(bl[ni][0], bl[ni][1], uBl + o);
        }
#pragma unroll
        for (int mi = 0; mi < 4; mi++)
#pragma unroll
            for (int ni = 0; ni < 4; ni++) {
                mma16816(acc[mi][ni], ah[mi][0], ah[mi][1], ah[mi][2], ah[mi][3], bh[ni][0], bh[ni][1]);
                mma16816(acc[mi][ni], ah[mi][0], ah[mi][1], ah[mi][2], ah[mi][3], bl[ni][0], bl[ni][1]);
                mma16816(acc[mi][ni], al[mi][0], al[mi][1], al[mi][2], al[mi][3], bh[ni][0], bh[ni][1]);
            }
    }

    // ---- epilogue: D fragment -> Y[m][n] ----
    int grp = lane >> 2, tig = lane & 3;
#pragma unroll
    for (int mi = 0; mi < 4; mi++) {
        int r0 = m0 + mBase + mi * 16 + grp;
        int r1 = r0 + 8;
#pragma unroll
        for (int ni = 0; ni < 4; ni++) {
            int col = n0 + nBase + ni * 8 + tig * 2;
            if (r0 < Mvalid) {
                float2 v0 = make_float2(acc[mi][ni][0], acc[mi][ni][1]);
                *(float2*)(Y + (size_t)r0 * NPIX_ + col) = v0;
            }
            if (r1 < Mvalid) {
                float2 v1 = make_float2(acc[mi][ni][2], acc[mi][ni][3]);
                *(float2*)(Y + (size_t)r1 * NPIX_ + col) = v1;
            }
        }
    }
}

// ---------------- router ----------------
__global__ void router_kernel(const float* __restrict__ x,
                              const float* __restrict__ rw_main,
                              const float* __restrict__ rw_aux,
                              const int*   __restrict__ task_id,
                              float* __restrict__ gates) {
    int n = blockIdx.x * blockDim.x + threadIdx.x;
    int b = blockIdx.y;
    const float* rw = (task_id[0] == 0) ? rw_main : rw_aux;
    __shared__ float w[HEADS_ * C_];
    for (int i = threadIdx.x; i < HEADS_ * C_; i += blockDim.x) w[i] = rw[i];
    __syncthreads();
    const float* xb = x + (size_t)b * C_ * NPIX_ + n;
    float logit[HEADS_];
#pragma unroll
    for (int h = 0; h < HEADS_; h++) logit[h] = 0.f;
    for (int c = 0; c < C_; c++) {
        float xv = xb[(size_t)c * NPIX_];
#pragma unroll
        for (int h = 0; h < HEADS_; h++) logit[h] += xv * w[h * C_ + c];
    }
    float mx = logit[0];
#pragma unroll
    for (int h = 1; h < HEADS_; h++) mx = fmaxf(mx, logit[h]);
    float p[HEADS_]; float s = 0.f;
#pragma unroll
    for (int h = 0; h < HEADS_; h++) { p[h] = expf(logit[h] - mx); s += p[h]; }
    float inv = 1.f / s;
#pragma unroll
    for (int h = 0; h < HEADS_; h++) p[h] *= inv;
    int h1 = 0;
#pragma unroll
    for (int h = 1; h < HEADS_; h++) if (p[h] > p[h1]) h1 = h;
    int h2 = -1;
#pragma unroll
    for (int h = 0; h < HEADS_; h++) if (h != h1 && (h2 < 0 || p[h] > p[h2])) h2 = h;
    float denom = fmaxf(p[h1] + p[h2], 1.1920929e-07f);
    float gscale = 2.0f / denom;
#pragma unroll
    for (int h = 0; h < HEADS_; h++) {
        float g = (h == h1) ? p[h1] * gscale : ((h == h2) ? p[h2] * gscale : 0.f);
        gates[((size_t)b * HEADS_ + h) * NPIX_ + n] = g;
    }
}

// ---------------- depthwise 3x3 ----------------
__global__ void dwconv_kernel(const float* __restrict__ in,
                              const float* __restrict__ wgt,
                              float* __restrict__ out) {
    int idx = blockIdx.x * blockDim.x + threadIdx.x;
    int ch  = blockIdx.y;
    int b   = blockIdx.z;
    int hh = idx >> 7, ww = idx & 127;
    const float* src = in + ((size_t)b * C3_ + ch) * NPIX_;
    const float* kw  = wgt + ch * 9;
    float acc = 0.f;
#pragma unroll
    for (int dy = -1; dy <= 1; dy++) {
        int y = hh + dy;
        if (y < 0 || y >= HW_) continue;
#pragma unroll
        for (int dx = -1; dx <= 1; dx++) {
            int xw = ww + dx;
            if (xw < 0 || xw >= HW_) continue;
            acc += src[y * HW_ + xw] * kw[(dy + 1) * 3 + (dx + 1)];
        }
    }
    out[((size_t)b * C3_ + ch) * NPIX_ + idx] = acc;
}

// ---------------- 1/L2 norms ----------------
__global__ void norm_kernel(const float* __restrict__ qkv2, float* __restrict__ rnorm) {
    int r = blockIdx.x;
    int b = r / (2 * C_), ch = r % (2 * C_);
    const float* src = qkv2 + ((size_t)b * C3_ + ch) * NPIX_;
    float s = 0.f;
    for (int i = threadIdx.x; i < NPIX_; i += blockDim.x) { float v = src[i]; s += v * v; }
    __shared__ float red[256];
    red[threadIdx.x] = s;
    __syncthreads();
    for (int o = 128; o > 0; o >>= 1) {
        if (threadIdx.x < o) red[threadIdx.x] += red[threadIdx.x + o];
        __syncthreads();
    }
    if (threadIdx.x == 0) rnorm[r] = 1.f / fmaxf(sqrtf(red[0]), 1e-12f);
}

// ---------------- Gram + softmax ----------------
__global__ void gram_softmax_kernel(const float* __restrict__ qkv2,
                                    const float* __restrict__ rnorm,
                                    float* __restrict__ attn) {
    int h = blockIdx.x, b = blockIdx.y;
    int t = threadIdx.x;
    int c = t / HD_, d = t % HD_;
    const int CH = 128;
    __shared__ float qs[HD_][CH + 1];
    __shared__ float ks[HD_][CH + 1];
    const float* qb = qkv2 + ((size_t)b * C3_ + h * HD_) * NPIX_;
    const float* kb = qkv2 + ((size_t)b * C3_ + C_ + h * HD_) * NPIX_;
    float acc = 0.f;
    for (int n0 = 0; n0 < NPIX_; n0 += CH) {
        for (int i = t; i < HD_ * CH; i += 576) {
            int cc = i / CH, nn = i % CH;
            qs[cc][nn] = qb[(size_t)cc * NPIX_ + n0 + nn];
            ks[cc][nn] = kb[(size_t)cc * NPIX_ + n0 + nn];
        }
        __syncthreads();
#pragma unroll 8
        for (int nn = 0; nn < CH; nn++) acc += qs[c][nn] * ks[d][nn];
        __syncthreads();
    }
    float rq = rnorm[b * 2 * C_ + h * HD_ + c];
    float rk = rnorm[b * 2 * C_ + C_ + h * HD_ + d];
    __shared__ float S[HD_][HD_ + 1];
    S[c][d] = acc * rq * rk * 0.20412414523193154f;
    __syncthreads();
    if (d == 0) {
        float m = -1e30f;
        for (int j = 0; j < HD_; j++) m = fmaxf(m, S[c][j]);
        float ss = 0.f;
        for (int j = 0; j < HD_; j++) { float e = expf(S[c][j] - m); S[c][j] = e; ss += e; }
        float inv = 1.f / ss;
        for (int j = 0; j < HD_; j++) S[c][j] *= inv;
    }
    __syncthreads();
    attn[(((size_t)b * HEADS_ + h) * HD_ + c) * HD_ + d] = S[c][d];
}

// ---------------- out = (attn @ v) * gate -> transposed split-bf16 ----------------
__global__ void av_kernel(const float* __restrict__ qkv2,
                          const float* __restrict__ attn,
                          const float* __restrict__ gates,
                          __nv_bfloat16* __restrict__ ot_hi,
                          __nv_bfloat16* __restrict__ ot_lo) {
    int n = blockIdx.x * blockDim.x + threadIdx.x;
    int h = blockIdx.y, b = blockIdx.z;
    __shared__ float A[HD_][HD_];
    const float* ab = attn + ((size_t)b * HEADS_ + h) * HD_ * HD_;
    for (int i = threadIdx.x; i < HD_ * HD_; i += blockDim.x) A[i / HD_][i % HD_] = ab[i];
    __syncthreads();
    const float* v = qkv2 + ((size_t)b * C3_ + 2 * C_ + h * HD_) * NPIX_ + n;
    float acc[HD_];
#pragma unroll
    for (int c = 0; c < HD_; c++) acc[c] = 0.f;
#pragma unroll
    for (int d = 0; d < HD_; d++) {
        float vv = v[(size_t)d * NPIX_];
#pragma unroll
        for (int c = 0; c < HD_; c++) acc[c] += A[c][d] * vv;
    }
    float g = gates[((size_t)b * HEADS_ + h) * NPIX_ + n];
    size_t o = ((size_t)b * NPIX_ + n) * K_ + h * HD_;
#pragma unroll
    for (int c = 0; c < HD_; c += 2) {
        float v0 = acc[c] * g, v1 = acc[c + 1] * g;
        __nv_bfloat16 h0 = __float2bfloat16(v0), h1 = __float2bfloat16(v1);
        __nv_bfloat162 hp; hp.x = h0; hp.y = h1;
        *(__nv_bfloat162*)(ot_hi + o + c) = hp;
        __nv_bfloat162 lp;
        lp.x = __float2bfloat16(v0 - __bfloat162float(h0));
        lp.y = __float2bfloat16(v1 - __bfloat162float(h1));
        *(__nv_bfloat162*)(ot_lo + o + c) = lp;
    }
}

// ---------------- launch ----------------
extern "C" void kernel_launch(void* const* d_in, const int* in_sizes, int n_in,
                              void* d_out, int out_size) {
    const float* x       = (const float*)d_in[0];
    const float* qkv_w   = (const float*)d_in[1];
    const float* dw_w    = (const float*)d_in[2];
    const float* proj_w  = (const float*)d_in[3];
    const float* rw_main = (const float*)d_in[4];
    const float* rw_aux  = (const float*)d_in[5];
    const int*   task_id = (const int*)d_in[6];
    float* out = (float*)d_out;

    float *qkv, *qkv2, *gates, *rnorm, *attn;
    __nv_bfloat16 *xt_hi, *xt_lo, *ot_hi, *ot_lo, *wq_hi, *wq_lo, *wp_hi, *wp_lo;
    cudaGetSymbolAddress((void**)&qkv,   g_qkv);
    cudaGetSymbolAddress((void**)&qkv2,  g_qkv2);
    cudaGetSymbolAddress((void**)&gates, g_gates);
    cudaGetSymbolAddress((void**)&rnorm, g_rnorm);
    cudaGetSymbolAddress((void**)&attn,  g_attn);
    cudaGetSymbolAddress((void**)&xt_hi, g_xt_hi);
    cudaGetSymbolAddress((void**)&xt_lo, g_xt_lo);
    cudaGetSymbolAddress((void**)&ot_hi, g_ot_hi);
    cudaGetSymbolAddress((void**)&ot_lo, g_ot_lo);
    cudaGetSymbolAddress((void**)&wq_hi, g_wq_hi);
    cudaGetSymbolAddress((void**)&wq_lo, g_wq_lo);
    cudaGetSymbolAddress((void**)&wp_hi, g_wp_hi);
    cudaGetSymbolAddress((void**)&wp_lo, g_wp_lo);

    cudaFuncSetAttribute(gemm_mma, cudaFuncAttributeMaxDynamicSharedMemorySize, SM_DYN_SZ);

    // weight splits (tiny)
    split_w_kernel<<<(640 * K_ + 255) / 256, 256>>>(qkv_w, wq_hi, wq_lo, C3_, 640);
    split_w_kernel<<<(256 * K_ + 255) / 256, 256>>>(proj_w, wp_hi, wp_lo, C_, 256);
    // x transpose + split
    split_transpose_x<<<dim3(NPIX_ / 32, B_), 256>>>(x, xt_hi, xt_lo);
    // router gates
    router_kernel<<<dim3(NPIX_ / 256, B_), 256>>>(x, rw_main, rw_aux, task_id, gates);
    // qkv = W_qkv @ x   (HMMA split-bf16)
    gemm_mma<<<dim3(NPIX_ / BN_, 640 / BM_, B_), 256, SM_DYN_SZ>>>(wq_hi, wq_lo, xt_hi, xt_lo, qkv, C3_);
    // depthwise 3x3
    dwconv_kernel<<<dim3(NPIX_ / 256, C3_, B_), 256>>>(qkv, dw_w, qkv2);
    // q,k norms
    norm_kernel<<<B_ * 2 * C_, 256>>>(qkv2, rnorm);
    // Gram + softmax
    gram_softmax_kernel<<<dim3(HEADS_, B_), 576>>>(qkv2, rnorm, attn);
    // attn @ v (gated) -> transposed split bf16
    av_kernel<<<dim3(NPIX_ / 256, HEADS_, B_), 256>>>(qkv2, attn, gates, ot_hi, ot_lo);
    // out = W_proj @ obuf  (HMMA split-bf16)
    gemm_mma<<<dim3(NPIX_ / BN_, 256 / BM_, B_), 256, SM_DYN_SZ>>>(wp_hi, wp_lo, ot_hi, ot_lo, out, C_);
}

// round 5
// speedup vs baseline: 2.7000x; 1.6454x over previous
#include <cuda_runtime.h>
#include <cuda_bf16.h>
#include <math.h>
#include <stdint.h>

#define B_     8
#define C_     192
#define HEADS_ 8
#define HD_    24
#define HW_    128
#define NPIX_  16384
#define C3_    576
#define K_     192

// GEMM tiling
#define BM_ 128
#define BN_ 128
#define LDS_ 200                 // padded row length in bf16 (400 B, conflict-free ldmatrix)
#define TILE_B_ (BM_ * LDS_ * 2) // 51200 bytes per tile
#define SM_DYN_SZ (4 * TILE_B_)  // 204800

#define GPAD_ 257
#define GSM_SZ (2 * HD_ * GPAD_ * 4)   // 49344 bytes

// ---------------- scratch (static __device__ — no allocations) ----------------
__device__ float g_qkv [(size_t)B_ * C3_ * NPIX_];
__device__ float g_qkv2[(size_t)B_ * C3_ * NPIX_];
__device__ float g_gates[(size_t)B_ * HEADS_ * NPIX_];
__device__ float g_ss  [B_ * 2 * C_ * 4];                       // sumsq partials (4 per channel)
__device__ float g_gram_part[(size_t)B_ * HEADS_ * 64 * HD_ * HD_];
__device__ float g_attn [B_ * HEADS_ * HD_ * HD_];
__device__ __nv_bfloat16 g_xt_hi[(size_t)B_ * NPIX_ * K_];
__device__ __nv_bfloat16 g_xt_lo[(size_t)B_ * NPIX_ * K_];
__device__ __nv_bfloat16 g_ot_hi[(size_t)B_ * NPIX_ * K_];
__device__ __nv_bfloat16 g_ot_lo[(size_t)B_ * NPIX_ * K_];
__device__ __nv_bfloat16 g_wq_hi[640 * K_];
__device__ __nv_bfloat16 g_wq_lo[640 * K_];
__device__ __nv_bfloat16 g_wp_hi[256 * K_];
__device__ __nv_bfloat16 g_wp_lo[256 * K_];

// ---------------- helpers ----------------
__device__ __forceinline__ uint32_t smem_u32(const void* p) {
    uint32_t a;
    asm("{ .reg .u64 t; cvta.to.shared.u64 t, %1; cvt.u32.u64 %0, t; }" : "=r"(a) : "l"(p));
    return a;
}
__device__ __forceinline__ void ldm_x4(uint32_t& r0, uint32_t& r1, uint32_t& r2, uint32_t& r3, uint32_t a) {
    asm volatile("ldmatrix.sync.aligned.m8n8.x4.shared.b16 {%0,%1,%2,%3}, [%4];"
                 : "=r"(r0), "=r"(r1), "=r"(r2), "=r"(r3) : "r"(a));
}
__device__ __forceinline__ void ldm_x2(uint32_t& r0, uint32_t& r1, uint32_t a) {
    asm volatile("ldmatrix.sync.aligned.m8n8.x2.shared.b16 {%0,%1}, [%2];"
                 : "=r"(r0), "=r"(r1) : "r"(a));
}
__device__ __forceinline__ void mma16816(float* c, uint32_t a0, uint32_t a1, uint32_t a2, uint32_t a3,
                                         uint32_t b0, uint32_t b1) {
    asm volatile("mma.sync.aligned.m16n8k16.row.col.f32.bf16.bf16.f32 "
                 "{%0,%1,%2,%3}, {%4,%5,%6,%7}, {%8,%9}, {%0,%1,%2,%3};"
                 : "+f"(c[0]), "+f"(c[1]), "+f"(c[2]), "+f"(c[3])
                 : "r"(a0), "r"(a1), "r"(a2), "r"(a3), "r"(b0), "r"(b1));
}

// ---------------- split fp32 -> bf16 hi/lo for weights (padded rows zeroed) ----------------
__global__ void split_w_kernel(const float* __restrict__ w, __nv_bfloat16* __restrict__ hi,
                               __nv_bfloat16* __restrict__ lo, int M, int Mpad) {
    int i = blockIdx.x * 256 + threadIdx.x;
    if (i >= Mpad * K_) return;
    float v = (i < M * K_) ? w[i] : 0.f;
    __nv_bfloat16 h = __float2bfloat16(v);
    hi[i] = h;
    lo[i] = __float2bfloat16(v - __bfloat162float(h));
}

// ---------------- fused: transpose+split x AND router gates ----------------
__global__ void fused_tr_router(const float* __restrict__ x,
                                const float* __restrict__ rw_main,
                                const float* __restrict__ rw_aux,
                                const int*   __restrict__ task_id,
                                __nv_bfloat16* __restrict__ hi, __nv_bfloat16* __restrict__ lo,
                                float* __restrict__ gates) {
    int b = blockIdx.y;
    int n0 = blockIdx.x * 32;
    __shared__ float tile[C_][33];
    __shared__ float w[HEADS_ * C_];
    __shared__ float sg[HEADS_][32];
    int t = threadIdx.x;
    const float* rw = (task_id[0] == 0) ? rw_main : rw_aux;
    for (int i = t; i < HEADS_ * C_; i += 256) w[i] = rw[i];
    for (int i = t; i < C_ * 32; i += 256) {
        int c = i >> 5, j = i & 31;
        tile[c][j] = x[((size_t)b * C_ + c) * NPIX_ + n0 + j];
    }
    __syncthreads();

    // transpose + split writes
    for (int i = t; i < 32 * C_; i += 256) {
        int j = i / C_, c = i - j * C_;
        float v = tile[c][j];
        __nv_bfloat16 h = __float2bfloat16(v);
        size_t o = ((size_t)b * NPIX_ + n0 + j) * K_ + c;
        hi[o] = h;
        lo[o] = __float2bfloat16(v - __bfloat162float(h));
    }

    // router: 8 threads per pixel
    int j = t >> 3, k = t & 7;
    float lg[HEADS_];
#pragma unroll
    for (int h = 0; h < HEADS_; h++) lg[h] = 0.f;
#pragma unroll
    for (int i = 0; i < 24; i++) {
        int c = k + i * 8;
        float xv = tile[c][j];
#pragma unroll
        for (int h = 0; h < HEADS_; h++) lg[h] += xv * w[h * C_ + c];
    }
#pragma unroll
    for (int h = 0; h < HEADS_; h++) {
        lg[h] += __shfl_down_sync(0xffffffffu, lg[h], 4, 8);
        lg[h] += __shfl_down_sync(0xffffffffu, lg[h], 2, 8);
        lg[h] += __shfl_down_sync(0xffffffffu, lg[h], 1, 8);
    }
    if (k == 0) {
        float mx = lg[0];
#pragma unroll
        for (int h = 1; h < HEADS_; h++) mx = fmaxf(mx, lg[h]);
        float p[HEADS_]; float s = 0.f;
#pragma unroll
        for (int h = 0; h < HEADS_; h++) { p[h] = expf(lg[h] - mx); s += p[h]; }
        float inv = 1.f / s;
#pragma unroll
        for (int h = 0; h < HEADS_; h++) p[h] *= inv;
        int h1 = 0;
#pragma unroll
        for (int h = 1; h < HEADS_; h++) if (p[h] > p[h1]) h1 = h;
        int h2 = -1;
#pragma unroll
        for (int h = 0; h < HEADS_; h++) if (h != h1 && (h2 < 0 || p[h] > p[h2])) h2 = h;
        float denom = fmaxf(p[h1] + p[h2], 1.1920929e-07f);
        float gscale = 2.0f / denom;
#pragma unroll
        for (int h = 0; h < HEADS_; h++)
            sg[h][j] = (h == h1) ? p[h1] * gscale : ((h == h2) ? p[h2] * gscale : 0.f);
    }
    __syncthreads();
    {   // coalesced gate store: 256 threads = 8 heads x 32 pixels
        int h = t >> 5, jj = t & 31;
        gates[((size_t)b * HEADS_ + h) * NPIX_ + n0 + jj] = sg[h][jj];
    }
}

// ---------------- HMMA split-bf16 GEMM, B-resident m-loop ----------------
// A: W [Mpad,192] bf16 hi/lo row-major. B: Xt[b] [NPIX,192] bf16 hi/lo row-major.
// Y[b] = W * Xt^T, per-batch slab of Mvalid x NPIX.
__global__ void __launch_bounds__(256, 1)
gemm_mma(const __nv_bfloat16* __restrict__ Ahi, const __nv_bfloat16* __restrict__ Alo,
         const __nv_bfloat16* __restrict__ Bhi, const __nv_bfloat16* __restrict__ Blo,
         float* __restrict__ Y, int Mvalid, int mtiles) {
    extern __shared__ char dsm[];
    char* sAh = dsm;
    char* sAl = dsm + TILE_B_;
    char* sBh = dsm + 2 * TILE_B_;
    char* sBl = dsm + 3 * TILE_B_;

    int t = threadIdx.x, wid = t >> 5, lane = t & 31;
    int n0 = blockIdx.x * BN_;
    int b  = blockIdx.z;

    Y += (size_t)b * Mvalid * NPIX_;

    // ---- load B tiles once ----
    const int4* srcB_hi = (const int4*)(Bhi + ((size_t)b * NPIX_ + n0) * K_);
    const int4* srcB_lo = (const int4*)(Blo + ((size_t)b * NPIX_ + n0) * K_);
#pragma unroll 4
    for (int i = t; i < 3072; i += 256) {
        int r = i / 24, ck = i - r * 24;
        int off = r * 400 + ck * 16;
        *(int4*)(sBh + off) = srcB_hi[i];
        *(int4*)(sBl + off) = srcB_lo[i];
    }

    int wm = wid >> 2, wn = wid & 3;
    int mBase = wm * 64;
    int nBase = wn * 32;
    int aRow = mBase + (lane & 15);
    int aK   = (lane >> 4) * 8;
    int bRow = nBase + (lane & 7);
    int bK   = ((lane >> 3) & 1) * 8;
    uint32_t aOffBase = (uint32_t)(aRow * 400 + aK * 2);
    uint32_t bOffBase = (uint32_t)(bRow * 400 + bK * 2);
    uint32_t uAh = smem_u32(sAh), uAl = smem_u32(sAl);
    uint32_t uBh = smem_u32(sBh), uBl = smem_u32(sBl);
    int grp = lane >> 2, tig = lane & 3;

    for (int mt = 0; mt < mtiles; mt++) {
        int m0 = mt * BM_;
        __syncthreads();   // B ready (first iter); sA free (later iters)
        const int4* srcA_hi = (const int4*)(Ahi + (size_t)m0 * K_);
        const int4* srcA_lo = (const int4*)(Alo + (size_t)m0 * K_);
#pragma unroll 4
        for (int i = t; i < 3072; i += 256) {
            int r = i / 24, ck = i - r * 24;
            int off = r * 400 + ck * 16;
            *(int4*)(sAh + off) = srcA_hi[i];
            *(int4*)(sAl + off) = srcA_lo[i];
        }
        __syncthreads();

        float acc[4][4][4];
#pragma unroll
        for (int mi = 0; mi < 4; mi++)
#pragma unroll
            for (int ni = 0; ni < 4; ni++)
#pragma unroll
                for (int jj = 0; jj < 4; jj++) acc[mi][ni][jj] = 0.f;

#pragma unroll
        for (int kc = 0; kc < 12; kc++) {
            uint32_t kByte = kc * 32;
            uint32_t ah[4][4], al[4][4], bh[4][2], bl[4][2];
#pragma unroll
            for (int mi = 0; mi < 4; mi++) {
                uint32_t o = aOffBase + mi * (16 * 400) + kByte;
                ldm_x4(ah[mi][0], ah[mi][1], ah[mi][2], ah[mi][3], uAh + o);
                ldm_x4(al[mi][0], al[mi][1], al[mi][2], al[mi][3], uAl + o);
            }
#pragma unroll
            for (int ni = 0; ni < 4; ni++) {
                uint32_t o = bOffBase + ni * (8 * 400) + kByte;
                ldm_x2(bh[ni][0], bh[ni][1], uBh + o);
                ldm_x2(bl[ni][0], bl[ni][1], uBl + o);
            }
#pragma unroll
            for (int mi = 0; mi < 4; mi++)
#pragma unroll
                for (int ni = 0; ni < 4; ni++) {
                    mma16816(acc[mi][ni], ah[mi][0], ah[mi][1], ah[mi][2], ah[mi][3], bh[ni][0], bh[ni][1]);
                    mma16816(acc[mi][ni], ah[mi][0], ah[mi][1], ah[mi][2], ah[mi][3], bl[ni][0], bl[ni][1]);
                    mma16816(acc[mi][ni], al[mi][0], al[mi][1], al[mi][2], al[mi][3], bh[ni][0], bh[ni][1]);
                }
        }

        // epilogue
#pragma unroll
        for (int mi = 0; mi < 4; mi++) {
            int r0 = m0 + mBase + mi * 16 + grp;
            int r1 = r0 + 8;
#pragma unroll
            for (int ni = 0; ni < 4; ni++) {
                int col = n0 + nBase + ni * 8 + tig * 2;
                if (r0 < Mvalid) {
                    float2 v0 = make_float2(acc[mi][ni][0], acc[mi][ni][1]);
                    *(float2*)(Y + (size_t)r0 * NPIX_ + col) = v0;
                }
                if (r1 < Mvalid) {
                    float2 v1 = make_float2(acc[mi][ni][2], acc[mi][ni][3]);
                    *(float2*)(Y + (size_t)r1 * NPIX_ + col) = v1;
                }
            }
        }
    }
}

// ---------------- depthwise 3x3, tiled smem, fused sumsq partials ----------------
#define TR_ 32
__global__ void dwconv_kernel(const float* __restrict__ in,
                              const float* __restrict__ wgt,
                              float* __restrict__ out,
                              float* __restrict__ ss) {
    __shared__ float s[TR_ + 2][HW_];
    __shared__ float red[8];
    int t = threadIdx.x;
    int ch = blockIdx.y, b = blockIdx.z;
    int y0 = blockIdx.x * TR_;
    const float* src = in + ((size_t)b * C3_ + ch) * NPIX_;
    float* dst = out + ((size_t)b * C3_ + ch) * NPIX_;
    float kw[9];
#pragma unroll
    for (int i = 0; i < 9; i++) kw[i] = wgt[ch * 9 + i];

    for (int i = t; i < (TR_ + 2) * HW_; i += 256) {
        int r = i >> 7, col = i & 127;
        int y = y0 - 1 + r;
        s[r][col] = (y >= 0 && y < HW_) ? src[y * HW_ + col] : 0.f;
    }
    __syncthreads();

    float ssum = 0.f;
    for (int p = t; p < TR_ * HW_; p += 256) {
        int r = p >> 7, col = p & 127;
        int sy = r + 1;
        float acc = 0.f;
        bool cl = col > 0, cr = col < HW_ - 1;
#pragma unroll
        for (int dy = 0; dy < 3; dy++) {
            const float* row = s[sy - 1 + dy];
            if (cl) acc += row[col - 1] * kw[dy * 3 + 0];
            acc += row[col] * kw[dy * 3 + 1];
            if (cr) acc += row[col + 1] * kw[dy * 3 + 2];
        }
        dst[(y0 + r) * HW_ + col] = acc;
        ssum += acc * acc;
    }

    if (ch < 2 * C_) {   // q,k channels: block-reduce sumsq -> deterministic partial
#pragma unroll
        for (int o = 16; o > 0; o >>= 1) ssum += __shfl_down_sync(0xffffffffu, ssum, o);
        if ((t & 31) == 0) red[t >> 5] = ssum;
        __syncthreads();
        if (t == 0) {
            float tot = 0.f;
#pragma unroll
            for (int i = 0; i < 8; i++) tot += red[i];
            ss[(b * 2 * C_ + ch) * 4 + blockIdx.x] = tot;
        }
    }
}

// ---------------- Gram partials: 24x24 over 256 pixels per block ----------------
__global__ void gram_partial(const float* __restrict__ qkv2, float* __restrict__ gpart) {
    extern __shared__ float gsm[];
    float* qs = gsm;                 // [24][257]
    float* ks = gsm + HD_ * GPAD_;   // [24][257]
    int sidx = blockIdx.x, h = blockIdx.y, b = blockIdx.z;
    int n0 = sidx * 256;
    int t = threadIdx.x;
    const float* qb = qkv2 + ((size_t)b * C3_ + h * HD_) * NPIX_ + n0;
    const float* kb = qkv2 + ((size_t)b * C3_ + C_ + h * HD_) * NPIX_ + n0;
    for (int i = t; i < HD_ * 256; i += 576) {
        int c = i >> 8, nn = i & 255;
        qs[c * GPAD_ + nn] = qb[(size_t)c * NPIX_ + nn];
        ks[c * GPAD_ + nn] = kb[(size_t)c * NPIX_ + nn];
    }
    __syncthreads();
    int c = t / HD_, d = t - c * HD_;
    const float* qr = qs + c * GPAD_;
    const float* kr = ks + d * GPAD_;
    float acc = 0.f;
#pragma unroll 8
    for (int nn = 0; nn < 256; nn++) acc += qr[nn] * kr[nn];
    gpart[(((size_t)(b * HEADS_ + h)) * 64 + sidx) * (HD_ * HD_) + t] = acc;
}

// ---------------- reduce partials + rnorm scale + softmax ----------------
__global__ void softmax_kernel(const float* __restrict__ gpart,
                               const float* __restrict__ ss,
                               float* __restrict__ attn) {
    int h = blockIdx.x, b = blockIdx.y;
    int t = threadIdx.x;
    int c = t / HD_, d = t - c * HD_;
    __shared__ float rq[HD_], rk[HD_];
    __shared__ float S[HD_][HD_ + 1];
    if (t < HD_) {
        const float* p = ss + (b * 2 * C_ + h * HD_ + t) * 4;
        float sum = p[0] + p[1] + p[2] + p[3];
        rq[t] = 1.f / fmaxf(sqrtf(sum), 1e-12f);
    } else if (t < 2 * HD_) {
        int d2 = t - HD_;
        const float* p = ss + (b * 2 * C_ + C_ + h * HD_ + d2) * 4;
        float sum = p[0] + p[1] + p[2] + p[3];
        rk[d2] = 1.f / fmaxf(sqrtf(sum), 1e-12f);
    }
    const float* gp = gpart + ((size_t)(b * HEADS_ + h)) * 64 * (HD_ * HD_) + t;
    float acc = 0.f;
#pragma unroll 8
    for (int sidx = 0; sidx < 64; sidx++) acc += gp[(size_t)sidx * (HD_ * HD_)];
    __syncthreads();
    S[c][d] = acc * rq[c] * rk[d] * 0.20412414523193154f;
    __syncthreads();
    if (d == 0) {
        float m = -1e30f;
        for (int jj = 0; jj < HD_; jj++) m = fmaxf(m, S[c][jj]);
        float sse = 0.f;
        for (int jj = 0; jj < HD_; jj++) { float e = expf(S[c][jj] - m); S[c][jj] = e; sse += e; }
        float inv = 1.f / sse;
        for (int jj = 0; jj < HD_; jj++) S[c][jj] *= inv;
    }
    __syncthreads();
    attn[(((size_t)b * HEADS_ + h) * HD_ + c) * HD_ + d] = S[c][d];
}

// ---------------- out = (attn @ v) * gate -> transposed split-bf16 ----------------
__global__ void av_kernel(const float* __restrict__ qkv2,
                          const float* __restrict__ attn,
                          const float* __restrict__ gates,
                          __nv_bfloat16* __restrict__ ot_hi,
                          __nv_bfloat16* __restrict__ ot_lo) {
    int n = blockIdx.x * blockDim.x + threadIdx.x;
    int h = blockIdx.y, b = blockIdx.z;
    __shared__ float A[HD_][HD_];
    const float* ab = attn + ((size_t)b * HEADS_ + h) * HD_ * HD_;
    for (int i = threadIdx.x; i < HD_ * HD_; i += blockDim.x) A[i / HD_][i % HD_] = ab[i];
    __syncthreads();
    const float* v = qkv2 + ((size_t)b * C3_ + 2 * C_ + h * HD_) * NPIX_ + n;
    float acc[HD_];
#pragma unroll
    for (int c = 0; c < HD_; c++) acc[c] = 0.f;
#pragma unroll
    for (int d = 0; d < HD_; d++) {
        float vv = v[(size_t)d * NPIX_];
#pragma unroll
        for (int c = 0; c < HD_; c++) acc[c] += A[c][d] * vv;
    }
    float g = gates[((size_t)b * HEADS_ + h) * NPIX_ + n];
    size_t o = ((size_t)b * NPIX_ + n) * K_ + h * HD_;
#pragma unroll
    for (int c = 0; c < HD_; c += 2) {
        float v0 = acc[c] * g, v1 = acc[c + 1] * g;
        __nv_bfloat16 h0 = __float2bfloat16(v0), h1 = __float2bfloat16(v1);
        __nv_bfloat162 hp; hp.x = h0; hp.y = h1;
        *(__nv_bfloat162*)(ot_hi + o + c) = hp;
        __nv_bfloat162 lp;
        lp.x = __float2bfloat16(v0 - __bfloat162float(h0));
        lp.y = __float2bfloat16(v1 - __bfloat162float(h1));
        *(__nv_bfloat162*)(ot_lo + o + c) = lp;
    }
}

// ---------------- launch ----------------
extern "C" void kernel_launch(void* const* d_in, const int* in_sizes, int n_in,
                              void* d_out, int out_size) {
    const float* x       = (const float*)d_in[0];
    const float* qkv_w   = (const float*)d_in[1];
    const float* dw_w    = (const float*)d_in[2];
    const float* proj_w  = (const float*)d_in[3];
    const float* rw_main = (const float*)d_in[4];
    const float* rw_aux  = (const float*)d_in[5];
    const int*   task_id = (const int*)d_in[6];
    float* out = (float*)d_out;

    float *qkv, *qkv2, *gates, *ss, *gpart, *attn;
    __nv_bfloat16 *xt_hi, *xt_lo, *ot_hi, *ot_lo, *wq_hi, *wq_lo, *wp_hi, *wp_lo;
    cudaGetSymbolAddress((void**)&qkv,   g_qkv);
    cudaGetSymbolAddress((void**)&qkv2,  g_qkv2);
    cudaGetSymbolAddress((void**)&gates, g_gates);
    cudaGetSymbolAddress((void**)&ss,    g_ss);
    cudaGetSymbolAddress((void**)&gpart, g_gram_part);
    cudaGetSymbolAddress((void**)&attn,  g_attn);
    cudaGetSymbolAddress((void**)&xt_hi, g_xt_hi);
    cudaGetSymbolAddress((void**)&xt_lo, g_xt_lo);
    cudaGetSymbolAddress((void**)&ot_hi, g_ot_hi);
    cudaGetSymbolAddress((void**)&ot_lo, g_ot_lo);
    cudaGetSymbolAddress((void**)&wq_hi, g_wq_hi);
    cudaGetSymbolAddress((void**)&wq_lo, g_wq_lo);
    cudaGetSymbolAddress((void**)&wp_hi, g_wp_hi);
    cudaGetSymbolAddress((void**)&wp_lo, g_wp_lo);

    cudaFuncSetAttribute(gemm_mma, cudaFuncAttributeMaxDynamicSharedMemorySize, SM_DYN_SZ);
    cudaFuncSetAttribute(gram_partial, cudaFuncAttributeMaxDynamicSharedMemorySize, GSM_SZ);

    split_w_kernel<<<(640 * K_ + 255) / 256, 256>>>(qkv_w, wq_hi, wq_lo, C3_, 640);
    split_w_kernel<<<(256 * K_ + 255) / 256, 256>>>(proj_w, wp_hi, wp_lo, C_, 256);
    // transpose/split x + router gates (single read of x)
    fused_tr_router<<<dim3(NPIX_ / 32, B_), 256>>>(x, rw_main, rw_aux, task_id, xt_hi, xt_lo, gates);
    // qkv = W_qkv @ x  (HMMA split-bf16, B-resident m-loop)
    gemm_mma<<<dim3(NPIX_ / BN_, 1, B_), 256, SM_DYN_SZ>>>(wq_hi, wq_lo, xt_hi, xt_lo, qkv, C3_, 5);
    // depthwise 3x3 + fused q/k sumsq partials
    dwconv_kernel<<<dim3(HW_ / TR_, C3_, B_), 256>>>(qkv, dw_w, qkv2, ss);
    // Gram partials
    gram_partial<<<dim3(64, HEADS_, B_), 576, GSM_SZ>>>(qkv2, gpart);
    // reduce + rnorm + softmax
    softmax_kernel<<<dim3(HEADS_, B_), 576>>>(gpart, ss, attn);
    // attn @ v (gated) -> transposed split bf16
    av_kernel<<<dim3(NPIX_ / 256, HEADS_, B_), 256>>>(qkv2, attn, gates, ot_hi, ot_lo);
    // out = W_proj @ obuf  (HMMA split-bf16)
    gemm_mma<<<dim3(NPIX_ / BN_, 1, B_), 256, SM_DYN_SZ>>>(wp_hi, wp_lo, ot_hi, ot_lo, out, C_, 2);
}

// round 7
// speedup vs baseline: 3.6400x; 1.3481x over previous
#include <cuda_runtime.h>
#include <cuda_bf16.h>
#include <math.h>
#include <stdint.h>

#define B_     8
#define C_     192
#define HEADS_ 8
#define HD_    24
#define HW_    128
#define NPIX_  16384
#define C3_    576
#define K_     192

// GEMM tiling: BM=64 (double-buffered A), BN=128, full K=192 resident
#define BN_ 128
#define BMq_ 64
#define BT_ROW_ 400                 // padded row bytes (200 bf16) — conflict-free ldmatrix
#define BTILE_ (BN_ * BT_ROW_)      // 51200: one 128-row operand tile
#define ATILE_ (BMq_ * BT_ROW_)     // 25600: one 64-row operand tile
#define SM_GEMM_ (2 * BTILE_ + 2 * 2 * ATILE_)   // B hi/lo + 2 bufs x (A hi/lo) = 204800

// gram
#define GSLICES_ 16
#define GROW_ 132
#define GSM_GRAM_ (4 * 2 * HD_ * GROW_ * 4)      // 4 groups x (q+k)[24][132] f32 = 101376

// ---------------- scratch (static __device__ — no allocations) ----------------
__device__ float g_qkv [(size_t)B_ * C3_ * NPIX_];
__device__ float g_qkv2[(size_t)B_ * C3_ * NPIX_];
__device__ float g_gates[(size_t)B_ * HEADS_ * NPIX_];
__device__ float g_ss  [B_ * 2 * C_ * 4];
__device__ float g_gram_part[(size_t)B_ * HEADS_ * GSLICES_ * HD_ * HD_];
__device__ float g_attn [B_ * HEADS_ * HD_ * HD_];
__device__ __nv_bfloat16 g_xt_hi[(size_t)B_ * NPIX_ * K_];
__device__ __nv_bfloat16 g_xt_lo[(size_t)B_ * NPIX_ * K_];
__device__ __nv_bfloat16 g_ot_hi[(size_t)B_ * NPIX_ * K_];
__device__ __nv_bfloat16 g_ot_lo[(size_t)B_ * NPIX_ * K_];
__device__ __nv_bfloat16 g_wq_hi[640 * K_];
__device__ __nv_bfloat16 g_wq_lo[640 * K_];
__device__ __nv_bfloat16 g_wp_hi[256 * K_];
__device__ __nv_bfloat16 g_wp_lo[256 * K_];

// ---------------- helpers ----------------
__device__ __forceinline__ uint32_t smem_u32(const void* p) {
    uint32_t a;
    asm("{ .reg .u64 t; cvta.to.shared.u64 t, %1; cvt.u32.u64 %0, t; }" : "=r"(a) : "l"(p));
    return a;
}
__device__ __forceinline__ void cp16(uint32_t d, const void* s) {
    asm volatile("cp.async.cg.shared.global [%0], [%1], 16;" :: "r"(d), "l"(s));
}
#define CP_COMMIT() asm volatile("cp.async.commit_group;" ::: "memory")
#define CP_WAIT(n)  asm volatile("cp.async.wait_group %0;" :: "n"(n) : "memory")
__device__ __forceinline__ void ldm_x4(uint32_t& r0, uint32_t& r1, uint32_t& r2, uint32_t& r3, uint32_t a) {
    asm volatile("ldmatrix.sync.aligned.m8n8.x4.shared.b16 {%0,%1,%2,%3}, [%4];"
                 : "=r"(r0), "=r"(r1), "=r"(r2), "=r"(r3) : "r"(a));
}
__device__ __forceinline__ void ldm_x2(uint32_t& r0, uint32_t& r1, uint32_t a) {
    asm volatile("ldmatrix.sync.aligned.m8n8.x2.shared.b16 {%0,%1}, [%2];"
                 : "=r"(r0), "=r"(r1) : "r"(a));
}
__device__ __forceinline__ void mma16816(float* c, uint32_t a0, uint32_t a1, uint32_t a2, uint32_t a3,
                                         uint32_t b0, uint32_t b1) {
    asm volatile("mma.sync.aligned.m16n8k16.row.col.f32.bf16.bf16.f32 "
                 "{%0,%1,%2,%3}, {%4,%5,%6,%7}, {%8,%9}, {%0,%1,%2,%3};"
                 : "+f"(c[0]), "+f"(c[1]), "+f"(c[2]), "+f"(c[3])
                 : "r"(a0), "r"(a1), "r"(a2), "r"(a3), "r"(b0), "r"(b1));
}

// ---------------- split fp32 -> bf16 hi/lo weights (padded rows zeroed) ----------------
__global__ void split_w_kernel(const float* __restrict__ w, __nv_bfloat16* __restrict__ hi,
                               __nv_bfloat16* __restrict__ lo, int M, int Mpad) {
    int i = blockIdx.x * 256 + threadIdx.x;
    if (i >= Mpad * K_) return;
    float v = (i < M * K_) ? w[i] : 0.f;
    __nv_bfloat16 h = __float2bfloat16(v);
    hi[i] = h;
    lo[i] = __float2bfloat16(v - __bfloat162float(h));
}

// ---------------- fused: transpose+split x AND router gates ----------------
__global__ void fused_tr_router(const float* __restrict__ x,
                                const float* __restrict__ rw_main,
                                const float* __restrict__ rw_aux,
                                const int*   __restrict__ task_id,
                                __nv_bfloat16* __restrict__ hi, __nv_bfloat16* __restrict__ lo,
                                float* __restrict__ gates) {
    int b = blockIdx.y;
    int n0 = blockIdx.x * 32;
    __shared__ float tile[C_][33];
    __shared__ float w[HEADS_ * C_];
    __shared__ float sg[HEADS_][32];
    int t = threadIdx.x;
    const float* rw = (task_id[0] == 0) ? rw_main : rw_aux;
    for (int i = t; i < HEADS_ * C_; i += 256) w[i] = rw[i];
    for (int i = t; i < C_ * 32; i += 256) {
        int c = i >> 5, j = i & 31;
        tile[c][j] = x[((size_t)b * C_ + c) * NPIX_ + n0 + j];
    }
    __syncthreads();

    for (int i = t; i < 32 * C_; i += 256) {
        int j = i / C_, c = i - j * C_;
        float v = tile[c][j];
        __nv_bfloat16 h = __float2bfloat16(v);
        size_t o = ((size_t)b * NPIX_ + n0 + j) * K_ + c;
        hi[o] = h;
        lo[o] = __float2bfloat16(v - __bfloat162float(h));
    }

    int j = t >> 3, k = t & 7;
    float lg[HEADS_];
#pragma unroll
    for (int h = 0; h < HEADS_; h++) lg[h] = 0.f;
#pragma unroll
    for (int i = 0; i < 24; i++) {
        int c = k + i * 8;
        float xv = tile[c][j];
#pragma unroll
        for (int h = 0; h < HEADS_; h++) lg[h] += xv * w[h * C_ + c];
    }
#pragma unroll
    for (int h = 0; h < HEADS_; h++) {
        lg[h] += __shfl_down_sync(0xffffffffu, lg[h], 4, 8);
        lg[h] += __shfl_down_sync(0xffffffffu, lg[h], 2, 8);
        lg[h] += __shfl_down_sync(0xffffffffu, lg[h], 1, 8);
    }
    if (k == 0) {
        float mx = lg[0];
#pragma unroll
        for (int h = 1; h < HEADS_; h++) mx = fmaxf(mx, lg[h]);
        float p[HEADS_]; float s = 0.f;
#pragma unroll
        for (int h = 0; h < HEADS_; h++) { p[h] = expf(lg[h] - mx); s += p[h]; }
        float inv = 1.f / s;
#pragma unroll
        for (int h = 0; h < HEADS_; h++) p[h] *= inv;
        int h1 = 0;
#pragma unroll
        for (int h = 1; h < HEADS_; h++) if (p[h] > p[h1]) h1 = h;
        int h2 = -1;
#pragma unroll
        for (int h = 0; h < HEADS_; h++) if (h != h1 && (h2 < 0 || p[h] > p[h2])) h2 = h;
        float denom = fmaxf(p[h1] + p[h2], 1.1920929e-07f);
        float gscale = 2.0f / denom;
#pragma unroll
        for (int h = 0; h < HEADS_; h++)
            sg[h][j] = (h == h1) ? p[h1] * gscale : ((h == h2) ? p[h2] * gscale : 0.f);
    }
    __syncthreads();
    {
        int h = t >> 5, jj = t & 31;
        gates[((size_t)b * HEADS_ + h) * NPIX_ + n0 + jj] = sg[h][jj];
    }
}

// ---------------- HMMA split-bf16 GEMM, cp.async double-buffered A ----------------
__global__ void __launch_bounds__(256, 1)
gemm_mma(const __nv_bfloat16* __restrict__ Ahi, const __nv_bfloat16* __restrict__ Alo,
         const __nv_bfloat16* __restrict__ Bhi, const __nv_bfloat16* __restrict__ Blo,
         float* __restrict__ Y, int Mvalid, int mtiles) {
    extern __shared__ char dsm[];
    uint32_t sb  = smem_u32(dsm);
    uint32_t uBh = sb, uBl = sb + BTILE_, uA = sb + 2 * BTILE_;

    int t = threadIdx.x, wid = t >> 5, lane = t & 31;
    int n0 = blockIdx.x * BN_;
    int b  = blockIdx.z;
    Y += (size_t)b * Mvalid * NPIX_;

    // ---- B tiles once via cp.async: 128 rows x 24 chunks ----
    const char* pBh = (const char*)(Bhi + ((size_t)b * NPIX_ + n0) * K_);
    const char* pBl = (const char*)(Blo + ((size_t)b * NPIX_ + n0) * K_);
    for (int i = t; i < 3072; i += 256) {
        int r = i / 24, ck = i - r * 24;
        uint32_t off = r * BT_ROW_ + ck * 16;
        cp16(uBh + off, pBh + i * 16);
        cp16(uBl + off, pBl + i * 16);
    }
    // ---- A m-tile 0 into buf 0: 64 rows x 24 chunks ----
    for (int i = t; i < 1536; i += 256) {
        int r = i / 24, ck = i - r * 24;
        uint32_t dst = uA + r * BT_ROW_ + ck * 16;
        cp16(dst, Ahi + (size_t)r * K_ + ck * 8);
        cp16(dst + ATILE_, Alo + (size_t)r * K_ + ck * 8);
    }
    CP_COMMIT();   // group: B + A0

    int wm = wid >> 2, wn = wid & 3;
    int mBase = wm * 32;
    int nBase = wn * 32;
    int aRowOff = (mBase + (lane & 15)) * BT_ROW_ + ((lane >> 4) * 8) * 2;
    int bRowOff = (nBase + (lane & 7)) * BT_ROW_ + (((lane >> 3) & 1) * 8) * 2;
    int grp = lane >> 2, tig = lane & 3;

    for (int mt = 0; mt < mtiles; mt++) {
        __syncthreads();   // all warps done with buffer (mt+1)&1 from iteration mt-1
        if (mt + 1 < mtiles) {
            int m0n = (mt + 1) * BMq_;
            uint32_t bufb = uA + ((mt + 1) & 1) * (2 * ATILE_);
            for (int i = t; i < 1536; i += 256) {
                int r = i / 24, ck = i - r * 24;
                uint32_t dst = bufb + r * BT_ROW_ + ck * 16;
                cp16(dst, Ahi + (size_t)(m0n + r) * K_ + ck * 8);
                cp16(dst + ATILE_, Alo + (size_t)(m0n + r) * K_ + ck * 8);
            }
            CP_COMMIT();
            CP_WAIT(1);
        } else {
            CP_WAIT(0);
        }
        __syncthreads();

        uint32_t uAh = uA + (mt & 1) * (2 * ATILE_);
        uint32_t uAl = uAh + ATILE_;
        int m0 = mt * BMq_;

        float acc[2][4][4];
#pragma unroll
        for (int mi = 0; mi < 2; mi++)
#pragma unroll
            for (int ni = 0; ni < 4; ni++)
#pragma unroll
                for (int jj = 0; jj < 4; jj++) acc[mi][ni][jj] = 0.f;

#pragma unroll
        for (int kc = 0; kc < 12; kc++) {
            uint32_t kByte = kc * 32;
            uint32_t ah[2][4], al[2][4], bh[4][2], bl[4][2];
#pragma unroll
            for (int mi = 0; mi < 2; mi++) {
                uint32_t o = aRowOff + mi * (16 * BT_ROW_) + kByte;
                ldm_x4(ah[mi][0], ah[mi][1], ah[mi][2], ah[mi][3], uAh + o);
                ldm_x4(al[mi][0], al[mi][1], al[mi][2], al[mi][3], uAl + o);
            }
#pragma unroll
            for (int ni = 0; ni < 4; ni++) {
                uint32_t o = bRowOff + ni * (8 * BT_ROW_) + kByte;
                ldm_x2(bh[ni][0], bh[ni][1], uBh + o);
                ldm_x2(bl[ni][0], bl[ni][1], uBl + o);
            }
#pragma unroll
            for (int mi = 0; mi < 2; mi++)
#pragma unroll
                for (int ni = 0; ni < 4; ni++) {
                    mma16816(acc[mi][ni], ah[mi][0], ah[mi][1], ah[mi][2], ah[mi][3], bh[ni][0], bh[ni][1]);
                    mma16816(acc[mi][ni], ah[mi][0], ah[mi][1], ah[mi][2], ah[mi][3], bl[ni][0], bl[ni][1]);
                    mma16816(acc[mi][ni], al[mi][0], al[mi][1], al[mi][2], al[mi][3], bh[ni][0], bh[ni][1]);
                }
        }

#pragma unroll
        for (int mi = 0; mi < 2; mi++) {
            int r0 = m0 + mBase + mi * 16 + grp;
            int r1 = r0 + 8;
#pragma unroll
            for (int ni = 0; ni < 4; ni++) {
                int col = n0 + nBase + ni * 8 + tig * 2;
                if (r0 < Mvalid)
                    *(float2*)(Y + (size_t)r0 * NPIX_ + col) = make_float2(acc[mi][ni][0], acc[mi][ni][1]);
                if (r1 < Mvalid)
                    *(float2*)(Y + (size_t)r1 * NPIX_ + col) = make_float2(acc[mi][ni][2], acc[mi][ni][3]);
            }
        }
    }
}

// ---------------- depthwise 3x3, tiled smem, float4, fused sumsq partials ----------------
#define TR_ 32
__global__ void dwconv_kernel(const float* __restrict__ in,
                              const float* __restrict__ wgt,
                              float* __restrict__ out,
                              float* __restrict__ ss) {
    __shared__ float s[TR_ + 2][HW_];
    __shared__ float red[8];
    int t = threadIdx.x;
    int ch = blockIdx.y, b = blockIdx.z;
    int y0 = blockIdx.x * TR_;
    const float* src = in + ((size_t)b * C3_ + ch) * NPIX_;
    float* dst = out + ((size_t)b * C3_ + ch) * NPIX_;
    float kw[9];
#pragma unroll
    for (int i = 0; i < 9; i++) kw[i] = wgt[ch * 9 + i];

    for (int i4 = t; i4 < (TR_ + 2) * 32; i4 += 256) {
        int r = i4 >> 5, c4 = i4 & 31;
        int y = y0 - 1 + r;
        float4 v = make_float4(0.f, 0.f, 0.f, 0.f);
        if (y >= 0 && y < HW_) v = *(const float4*)(src + y * HW_ + c4 * 4);
        *(float4*)(&s[r][c4 * 4]) = v;
    }
    __syncthreads();

    float ssum = 0.f;
    for (int p4 = t; p4 < TR_ * 32; p4 += 256) {
        int r = p4 >> 5, c4 = p4 & 31;
        int col = c4 * 4;
        float o[4];
#pragma unroll
        for (int px = 0; px < 4; px++) {
            int cc = col + px;
            float acc = 0.f;
            bool cl = cc > 0, cr = cc < HW_ - 1;
#pragma unroll
            for (int dy = 0; dy < 3; dy++) {
                const float* row = s[r + dy];
                if (cl) acc += row[cc - 1] * kw[dy * 3 + 0];
                acc += row[cc] * kw[dy * 3 + 1];
                if (cr) acc += row[cc + 1] * kw[dy * 3 + 2];
            }
            o[px] = acc;
            ssum += acc * acc;
        }
        *(float4*)(dst + (y0 + r) * HW_ + col) = make_float4(o[0], o[1], o[2], o[3]);
    }

    if (ch < 2 * C_) {
#pragma unroll
        for (int o = 16; o > 0; o >>= 1) ssum += __shfl_down_sync(0xffffffffu, ssum, o);
        if ((t & 31) == 0) red[t >> 5] = ssum;
        __syncthreads();
        if (t == 0) {
            float tot = 0.f;
#pragma unroll
            for (int i = 0; i < 8; i++) tot += red[i];
            ss[(b * 2 * C_ + ch) * 4 + blockIdx.x] = tot;
        }
    }
}

// ---------------- Gram partials: 3x3 register tiling, 4 groups/block ----------------
__global__ void gram_partial(const float* __restrict__ qkv2, float* __restrict__ gpart) {
    extern __shared__ float gsm[];
    int t = threadIdx.x;
    int grp = t >> 6, lt = t & 63;
    int h = blockIdx.y, b = blockIdx.z;
    int gi = blockIdx.x * 4 + grp;                 // 0..15
    float* qs = gsm + grp * (2 * HD_ * GROW_);
    float* ks = qs + HD_ * GROW_;
    const float* qb = qkv2 + ((size_t)b * C3_ + h * HD_) * NPIX_;
    const float* kb = qkv2 + ((size_t)b * C3_ + C_ + h * HD_) * NPIX_;
    int i = lt >> 3, j = lt & 7;

    float acc[3][3];
#pragma unroll
    for (int r = 0; r < 3; r++)
#pragma unroll
        for (int s2 = 0; s2 < 3; s2++) acc[r][s2] = 0.f;

    for (int chk = 0; chk < 8; chk++) {
        int n0 = gi * 1024 + chk * 128;
        __syncthreads();
        for (int idx = lt; idx < HD_ * 32; idx += 64) {
            int c = idx >> 5, v4 = idx & 31;
            *(float4*)(qs + c * GROW_ + v4 * 4) = *(const float4*)(qb + (size_t)c * NPIX_ + n0 + v4 * 4);
            *(float4*)(ks + c * GROW_ + v4 * 4) = *(const float4*)(kb + (size_t)c * NPIX_ + n0 + v4 * 4);
        }
        __syncthreads();
        const float* q0 = qs + (3 * i) * GROW_;
        const float* k0 = ks + (3 * j) * GROW_;
#pragma unroll 4
        for (int nn = 0; nn < 128; nn += 4) {
            float4 qv[3], kv[3];
#pragma unroll
            for (int r = 0; r < 3; r++) {
                qv[r] = *(const float4*)(q0 + r * GROW_ + nn);
                kv[r] = *(const float4*)(k0 + r * GROW_ + nn);
            }
#pragma unroll
            for (int r = 0; r < 3; r++)
#pragma unroll
                for (int s2 = 0; s2 < 3; s2++)
                    acc[r][s2] += qv[r].x * kv[s2].x + qv[r].y * kv[s2].y
                                + qv[r].z * kv[s2].z + qv[r].w * kv[s2].w;
        }
    }

    float* outp = gpart + (((size_t)(b * HEADS_ + h)) * GSLICES_ + gi) * (HD_ * HD_);
#pragma unroll
    for (int r = 0; r < 3; r++)
#pragma unroll
        for (int s2 = 0; s2 < 3; s2++)
            outp[(3 * i + r) * HD_ + 3 * j + s2] = acc[r][s2];
}

// ---------------- reduce partials + rnorm scale + softmax ----------------
__global__ void softmax_kernel(const float* __restrict__ gpart,
                               const float* __restrict__ ss,
                               float* __restrict__ attn) {
    int h = blockIdx.x, b = blockIdx.y;
    int t = threadIdx.x;
    int c = t / HD_, d = t - c * HD_;
    __shared__ float rq[HD_], rk[HD_];
    __shared__ float S[HD_][HD_ + 1];
    if (t < HD_) {
        const float* p = ss + (b * 2 * C_ + h * HD_ + t) * 4;
        rq[t] = 1.f / fmaxf(sqrtf(p[0] + p[1] + p[2] + p[3]), 1e-12f);
    } else if (t < 2 * HD_) {
        int d2 = t - HD_;
        const float* p = ss + (b * 2 * C_ + C_ + h * HD_ + d2) * 4;
        rk[d2] = 1.f / fmaxf(sqrtf(p[0] + p[1] + p[2] + p[3]), 1e-12f);
    }
    const float* gp = gpart + ((size_t)(b * HEADS_ + h)) * GSLICES_ * (HD_ * HD_) + t;
    float acc = 0.f;
#pragma unroll
    for (int sidx = 0; sidx < GSLICES_; sidx++) acc += gp[(size_t)sidx * (HD_ * HD_)];
    __syncthreads();
    S[c][d] = acc * rq[c] * rk[d] * 0.20412414523193154f;
    __syncthreads();
    if (d == 0) {
        float m = -1e30f;
        for (int jj = 0; jj < HD_; jj++) m = fmaxf(m, S[c][jj]);
        float sse = 0.f;
        for (int jj = 0; jj < HD_; jj++) { float e = expf(S[c][jj] - m); S[c][jj] = e; sse += e; }
        float inv = 1.f / sse;
        for (int jj = 0; jj < HD_; jj++) S[c][jj] *= inv;
    }
    __syncthreads();
    attn[(((size_t)b * HEADS_ + h) * HD_ + c) * HD_ + d] = S[c][d];
}

// ---------------- out = (attn @ v) * gate -> transposed split-bf16 (coalesced) ----------------
__global__ void av_kernel(const float* __restrict__ qkv2,
                          const float* __restrict__ attn,
                          const float* __restrict__ gates,
                          uint32_t* __restrict__ ot_hi,
                          uint32_t* __restrict__ ot_lo) {
    int n0 = blockIdx.x * 256;
    int n = n0 + threadIdx.x;
    int h = blockIdx.y, b = blockIdx.z;
    __shared__ float A[HD_][HD_];
    __shared__ uint32_t sh[256][13];
    __shared__ uint32_t sl[256][13];
    const float* ab = attn + ((size_t)b * HEADS_ + h) * HD_ * HD_;
    for (int i = threadIdx.x; i < HD_ * HD_; i += 256) A[i / HD_][i % HD_] = ab[i];
    __syncthreads();
    const float* v = qkv2 + ((size_t)b * C3_ + 2 * C_ + h * HD_) * NPIX_ + n;
    float acc[HD_];
#pragma unroll
    for (int c = 0; c < HD_; c++) acc[c] = 0.f;
#pragma unroll
    for (int d = 0; d < HD_; d++) {
        float vv = v[(size_t)d * NPIX_];
#pragma unroll
        for (int c = 0; c < HD_; c++) acc[c] += A[c][d] * vv;
    }
    float g = gates[((size_t)b * HEADS_ + h) * NPIX_ + n];
#pragma unroll
    for (int c2 = 0; c2 < 12; c2++) {
        float v0 = acc[2 * c2] * g, v1 = acc[2 * c2 + 1] * g;
        __nv_bfloat16 h0 = __float2bfloat16(v0), h1 = __float2bfloat16(v1);
        __nv_bfloat162 hp; hp.x = h0; hp.y = h1;
        sh[threadIdx.x][c2] = *(uint32_t*)&hp;
        __nv_bfloat162 lp;
        lp.x = __float2bfloat16(v0 - __bfloat162float(h0));
        lp.y = __float2bfloat16(v1 - __bfloat162float(h1));
        sl[threadIdx.x][c2] = *(uint32_t*)&lp;
    }
    __syncthreads();
    // coalesced write: ot rows are 96 uints; this head owns 12 uints at offset h*12
    for (int i = threadIdx.x; i < 256 * 12; i += 256) {
        int p = i / 12, c2 = i - p * 12;
        size_t o = ((size_t)b * NPIX_ + n0 + p) * 96 + h * 12 + c2;
        ot_hi[o] = sh[p][c2];
        ot_lo[o] = sl[p][c2];
    }
}

// ---------------- launch ----------------
extern "C" void kernel_launch(void* const* d_in, const int* in_sizes, int n_in,
                              void* d_out, int out_size) {
    const float* x       = (const float*)d_in[0];
    const float* qkv_w   = (const float*)d_in[1];
    const float* dw_w    = (const float*)d_in[2];
    const float* proj_w  = (const float*)d_in[3];
    const float* rw_main = (const float*)d_in[4];
    const float* rw_aux  = (const float*)d_in[5];
    const int*   task_id = (const int*)d_in[6];
    float* out = (float*)d_out;

    float *qkv, *qkv2, *gates, *ss, *gpart, *attn;
    __nv_bfloat16 *xt_hi, *xt_lo, *ot_hi, *ot_lo, *wq_hi, *wq_lo, *wp_hi, *wp_lo;
    cudaGetSymbolAddress((void**)&qkv,   g_qkv);
    cudaGetSymbolAddress((void**)&qkv2,  g_qkv2);
    cudaGetSymbolAddress((void**)&gates, g_gates);
    cudaGetSymbolAddress((void**)&ss,    g_ss);
    cudaGetSymbolAddress((void**)&gpart, g_gram_part);
    cudaGetSymbolAddress((void**)&attn,  g_attn);
    cudaGetSymbolAddress((void**)&xt_hi, g_xt_hi);
    cudaGetSymbolAddress((void**)&xt_lo, g_xt_lo);
    cudaGetSymbolAddress((void**)&ot_hi, g_ot_hi);
    cudaGetSymbolAddress((void**)&ot_lo, g_ot_lo);
    cudaGetSymbolAddress((void**)&wq_hi, g_wq_hi);
    cudaGetSymbolAddress((void**)&wq_lo, g_wq_lo);
    cudaGetSymbolAddress((void**)&wp_hi, g_wp_hi);
    cudaGetSymbolAddress((void**)&wp_lo, g_wp_lo);

    cudaFuncSetAttribute(gemm_mma, cudaFuncAttributeMaxDynamicSharedMemorySize, SM_GEMM_);
    cudaFuncSetAttribute(gram_partial, cudaFuncAttributeMaxDynamicSharedMemorySize, GSM_GRAM_);

    split_w_kernel<<<(640 * K_ + 255) / 256, 256>>>(qkv_w, wq_hi, wq_lo, C3_, 640);
    split_w_kernel<<<(256 * K_ + 255) / 256, 256>>>(proj_w, wp_hi, wp_lo, C_, 256);
    fused_tr_router<<<dim3(NPIX_ / 32, B_), 256>>>(x, rw_main, rw_aux, task_id, xt_hi, xt_lo, gates);
    // qkv = W_qkv @ x  (pipelined HMMA)
    gemm_mma<<<dim3(NPIX_ / BN_, 1, B_), 256, SM_GEMM_>>>(wq_hi, wq_lo, xt_hi, xt_lo, qkv, C3_, 10);
    // depthwise 3x3 + fused q/k sumsq partials
    dwconv_kernel<<<dim3(HW_ / TR_, C3_, B_), 256>>>(qkv, dw_w, qkv2, ss);
    // Gram partials (3x3 register tiling)
    gram_partial<<<dim3(4, HEADS_, B_), 256, GSM_GRAM_>>>(qkv2, gpart);
    softmax_kernel<<<dim3(HEADS_, B_), 576>>>(gpart, ss, attn);
    av_kernel<<<dim3(NPIX_ / 256, HEADS_, B_), 256>>>(qkv2, attn, gates, (uint32_t*)ot_hi, (uint32_t*)ot_lo);
    // out = W_proj @ obuf
    gemm_mma<<<dim3(NPIX_ / BN_, 1, B_), 256, SM_GEMM_>>>(wp_hi, wp_lo, ot_hi, ot_lo, out, C_, 4);
}

// round 8
// speedup vs baseline: 3.8271x; 1.0514x over previous
#include <cuda_runtime.h>
#include <cuda_bf16.h>
#include <math.h>
#include <stdint.h>

#define B_     8
#define C_     192
#define HEADS_ 8
#define HD_    24
#define HW_    128
#define NPIX_  16384
#define C3_    576
#define K_     192

// GEMM tiling: BM=64 (double-buffered A), BN=128, full K=192 resident
#define BN_ 128
#define BMq_ 64
#define BT_ROW_ 400
#define BTILE_ (BN_ * BT_ROW_)
#define ATILE_ (BMq_ * BT_ROW_)
#define SM_GEMM_ (2 * BTILE_ + 2 * 2 * ATILE_)   // 204800

// gram
#define GSLICES_ 16
#define GROW_ 132
#define GSM_GRAM_ (4 * 2 * HD_ * GROW_ * 4)

// ---------------- scratch ----------------
__device__ float g_qkv [(size_t)B_ * C3_ * NPIX_];
__device__ float g_qkv2[(size_t)B_ * C3_ * NPIX_];
__device__ float g_gates[(size_t)B_ * HEADS_ * NPIX_];
__device__ float g_ss  [B_ * 2 * C_ * 2];
__device__ float g_gram_part[(size_t)B_ * HEADS_ * GSLICES_ * HD_ * HD_];
__device__ float g_attn [B_ * HEADS_ * HD_ * HD_];
__device__ __nv_bfloat16 g_xt_hi[(size_t)B_ * NPIX_ * K_];
__device__ __nv_bfloat16 g_xt_lo[(size_t)B_ * NPIX_ * K_];
__device__ __nv_bfloat16 g_ot_hi[(size_t)B_ * NPIX_ * K_];
__device__ __nv_bfloat16 g_ot_lo[(size_t)B_ * NPIX_ * K_];
__device__ __nv_bfloat16 g_wq_hi[C3_ * K_];
__device__ __nv_bfloat16 g_wq_lo[C3_ * K_];
__device__ __nv_bfloat16 g_wp_hi[C_ * K_];
__device__ __nv_bfloat16 g_wp_lo[C_ * K_];

// ---------------- helpers ----------------
__device__ __forceinline__ uint32_t smem_u32(const void* p) {
    uint32_t a;
    asm("{ .reg .u64 t; cvta.to.shared.u64 t, %1; cvt.u32.u64 %0, t; }" : "=r"(a) : "l"(p));
    return a;
}
__device__ __forceinline__ void cp16(uint32_t d, const void* s) {
    asm volatile("cp.async.cg.shared.global [%0], [%1], 16;" :: "r"(d), "l"(s));
}
#define CP_COMMIT() asm volatile("cp.async.commit_group;" ::: "memory")
#define CP_WAIT(n)  asm volatile("cp.async.wait_group %0;" :: "n"(n) : "memory")
__device__ __forceinline__ void ldm_x4(uint32_t& r0, uint32_t& r1, uint32_t& r2, uint32_t& r3, uint32_t a) {
    asm volatile("ldmatrix.sync.aligned.m8n8.x4.shared.b16 {%0,%1,%2,%3}, [%4];"
                 : "=r"(r0), "=r"(r1), "=r"(r2), "=r"(r3) : "r"(a));
}
__device__ __forceinline__ void mma16816(float* c, uint32_t a0, uint32_t a1, uint32_t a2, uint32_t a3,
                                         uint32_t b0, uint32_t b1) {
    asm volatile("mma.sync.aligned.m16n8k16.row.col.f32.bf16.bf16.f32 "
                 "{%0,%1,%2,%3}, {%4,%5,%6,%7}, {%8,%9}, {%0,%1,%2,%3};"
                 : "+f"(c[0]), "+f"(c[1]), "+f"(c[2]), "+f"(c[3])
                 : "r"(a0), "r"(a1), "r"(a2), "r"(a3), "r"(b0), "r"(b1));
}

// ---------------- split fp32 -> bf16 hi/lo weights ----------------
__global__ void split_w_kernel(const float* __restrict__ w, __nv_bfloat16* __restrict__ hi,
                               __nv_bfloat16* __restrict__ lo, int total) {
    int i = blockIdx.x * 256 + threadIdx.x;
    if (i >= total) return;
    float v = w[i];
    __nv_bfloat16 h = __float2bfloat16(v);
    hi[i] = h;
    lo[i] = __float2bfloat16(v - __bfloat162float(h));
}

// ---------------- fused: transpose+split x AND router gates ----------------
__global__ void fused_tr_router(const float* __restrict__ x,
                                const float* __restrict__ rw_main,
                                const float* __restrict__ rw_aux,
                                const int*   __restrict__ task_id,
                                __nv_bfloat16* __restrict__ hi, __nv_bfloat16* __restrict__ lo,
                                float* __restrict__ gates) {
    int b = blockIdx.y;
    int n0 = blockIdx.x * 32;
    __shared__ float tile[C_][33];
    __shared__ float w[HEADS_ * C_];
    __shared__ float sg[HEADS_][32];
    int t = threadIdx.x;
    const float* rw = (task_id[0] == 0) ? rw_main : rw_aux;
    for (int i = t; i < HEADS_ * C_; i += 256) w[i] = rw[i];
    for (int i = t; i < C_ * 32; i += 256) {
        int c = i >> 5, j = i & 31;
        tile[c][j] = x[((size_t)b * C_ + c) * NPIX_ + n0 + j];
    }
    __syncthreads();

    for (int i = t; i < 32 * C_; i += 256) {
        int j = i / C_, c = i - j * C_;
        float v = tile[c][j];
        __nv_bfloat16 h = __float2bfloat16(v);
        size_t o = ((size_t)b * NPIX_ + n0 + j) * K_ + c;
        hi[o] = h;
        lo[o] = __float2bfloat16(v - __bfloat162float(h));
    }

    int j = t >> 3, k = t & 7;
    float lg[HEADS_];
#pragma unroll
    for (int h = 0; h < HEADS_; h++) lg[h] = 0.f;
#pragma unroll
    for (int i = 0; i < 24; i++) {
        int c = k + i * 8;
        float xv = tile[c][j];
#pragma unroll
        for (int h = 0; h < HEADS_; h++) lg[h] += xv * w[h * C_ + c];
    }
#pragma unroll
    for (int h = 0; h < HEADS_; h++) {
        lg[h] += __shfl_down_sync(0xffffffffu, lg[h], 4, 8);
        lg[h] += __shfl_down_sync(0xffffffffu, lg[h], 2, 8);
        lg[h] += __shfl_down_sync(0xffffffffu, lg[h], 1, 8);
    }
    if (k == 0) {
        float mx = lg[0];
#pragma unroll
        for (int h = 1; h < HEADS_; h++) mx = fmaxf(mx, lg[h]);
        float p[HEADS_]; float s = 0.f;
#pragma unroll
        for (int h = 0; h < HEADS_; h++) { p[h] = expf(lg[h] - mx); s += p[h]; }
        float inv = 1.f / s;
#pragma unroll
        for (int h = 0; h < HEADS_; h++) p[h] *= inv;
        int h1 = 0;
#pragma unroll
        for (int h = 1; h < HEADS_; h++) if (p[h] > p[h1]) h1 = h;
        int h2 = -1;
#pragma unroll
        for (int h = 0; h < HEADS_; h++) if (h != h1 && (h2 < 0 || p[h] > p[h2])) h2 = h;
        float denom = fmaxf(p[h1] + p[h2], 1.1920929e-07f);
        float gscale = 2.0f / denom;
#pragma unroll
        for (int h = 0; h < HEADS_; h++)
            sg[h][j] = (h == h1) ? p[h1] * gscale : ((h == h2) ? p[h2] * gscale : 0.f);
    }
    __syncthreads();
    {
        int h = t >> 5, jj = t & 31;
        gates[((size_t)b * HEADS_ + h) * NPIX_ + n0 + jj] = sg[h][jj];
    }
}

// ---------------- HMMA split-bf16 GEMM: cp.async A pipeline + reg-buffered frags ----------------
__global__ void __launch_bounds__(256, 1)
gemm_mma(const __nv_bfloat16* __restrict__ Ahi, const __nv_bfloat16* __restrict__ Alo,
         const __nv_bfloat16* __restrict__ Bhi, const __nv_bfloat16* __restrict__ Blo,
         float* __restrict__ Y, int Mvalid, int mtiles) {
    extern __shared__ char dsm[];
    uint32_t sb  = smem_u32(dsm);
    uint32_t uBh = sb, uBl = sb + BTILE_, uA = sb + 2 * BTILE_;

    int t = threadIdx.x, wid = t >> 5, lane = t & 31;
    int n0 = blockIdx.x * BN_;
    int b  = blockIdx.z;
    Y += (size_t)b * Mvalid * NPIX_;

    // B tiles once via cp.async: 128 rows x 24 chunks
    const char* pBh = (const char*)(Bhi + ((size_t)b * NPIX_ + n0) * K_);
    const char* pBl = (const char*)(Blo + ((size_t)b * NPIX_ + n0) * K_);
    for (int i = t; i < 3072; i += 256) {
        int r = i / 24, ck = i - r * 24;
        uint32_t off = r * BT_ROW_ + ck * 16;
        cp16(uBh + off, pBh + i * 16);
        cp16(uBl + off, pBl + i * 16);
    }
    // A m-tile 0 into buf 0: 64 rows x 24 chunks
    for (int i = t; i < 1536; i += 256) {
        int r = i / 24, ck = i - r * 24;
        uint32_t dst = uA + r * BT_ROW_ + ck * 16;
        cp16(dst, Ahi + (size_t)r * K_ + ck * 8);
        cp16(dst + ATILE_, Alo + (size_t)r * K_ + ck * 8);
    }
    CP_COMMIT();

    int wm = wid >> 2, wn = wid & 3;
    int mBase = wm * 32;
    int nBase = wn * 32;
    uint32_t aRowOff = (mBase + (lane & 15)) * BT_ROW_ + (lane >> 4) * 16;
    // B via ldmatrix.x4: mats = (nfrag pair*2, kLo),(pair*2, kHi),(pair*2+1, kLo),(pair*2+1, kHi)
    uint32_t bAddr4 = (nBase + ((lane >> 4) & 1) * 8 + (lane & 7)) * BT_ROW_ + ((lane >> 3) & 1) * 16;
    int grp = lane >> 2, tig = lane & 3;

    for (int mt = 0; mt < mtiles; mt++) {
        __syncthreads();
        if (mt + 1 < mtiles) {
            int m0n = (mt + 1) * BMq_;
            uint32_t bufb = uA + ((mt + 1) & 1) * (2 * ATILE_);
            for (int i = t; i < 1536; i += 256) {
                int r = i / 24, ck = i - r * 24;
                uint32_t dst = bufb + r * BT_ROW_ + ck * 16;
                cp16(dst, Ahi + (size_t)(m0n + r) * K_ + ck * 8);
                cp16(dst + ATILE_, Alo + (size_t)(m0n + r) * K_ + ck * 8);
            }
            CP_COMMIT();
            CP_WAIT(1);
        } else {
            CP_WAIT(0);
        }
        __syncthreads();

        uint32_t uAh = uA + (mt & 1) * (2 * ATILE_);
        uint32_t uAl = uAh + ATILE_;
        int m0 = mt * BMq_;

        float acc[2][4][4];
#pragma unroll
        for (int mi = 0; mi < 2; mi++)
#pragma unroll
            for (int ni = 0; ni < 4; ni++)
#pragma unroll
                for (int jj = 0; jj < 4; jj++) acc[mi][ni][jj] = 0.f;

        // register double-buffered fragments
        uint32_t ah[2][2][4], al[2][2][4], bh[2][4][2], bl[2][4][2];

#define LOADF(KC, BUF) do {                                                          \
            uint32_t kByte = (KC) * 32;                                              \
            _Pragma("unroll")                                                        \
            for (int mi = 0; mi < 2; mi++) {                                         \
                uint32_t o = aRowOff + mi * (16 * BT_ROW_) + kByte;                  \
                ldm_x4(ah[BUF][mi][0], ah[BUF][mi][1], ah[BUF][mi][2], ah[BUF][mi][3], uAh + o); \
                ldm_x4(al[BUF][mi][0], al[BUF][mi][1], al[BUF][mi][2], al[BUF][mi][3], uAl + o); \
            }                                                                        \
            _Pragma("unroll")                                                        \
            for (int pr = 0; pr < 2; pr++) {                                         \
                uint32_t o = bAddr4 + pr * (16 * BT_ROW_) + kByte;                   \
                ldm_x4(bh[BUF][pr*2][0], bh[BUF][pr*2][1], bh[BUF][pr*2+1][0], bh[BUF][pr*2+1][1], uBh + o); \
                ldm_x4(bl[BUF][pr*2][0], bl[BUF][pr*2][1], bl[BUF][pr*2+1][0], bl[BUF][pr*2+1][1], uBl + o); \
            }                                                                        \
        } while (0)

        LOADF(0, 0);
#pragma unroll
        for (int kc = 0; kc < 12; kc++) {
            int cur = kc & 1;
            if (kc < 11) {
                int nxt = cur ^ 1;
                LOADF(kc + 1, nxt);
            }
#pragma unroll
            for (int mi = 0; mi < 2; mi++)
#pragma unroll
                for (int ni = 0; ni < 4; ni++) {
                    mma16816(acc[mi][ni], ah[cur][mi][0], ah[cur][mi][1], ah[cur][mi][2], ah[cur][mi][3],
                             bh[cur][ni][0], bh[cur][ni][1]);
                    mma16816(acc[mi][ni], ah[cur][mi][0], ah[cur][mi][1], ah[cur][mi][2], ah[cur][mi][3],
                             bl[cur][ni][0], bl[cur][ni][1]);
                    mma16816(acc[mi][ni], al[cur][mi][0], al[cur][mi][1], al[cur][mi][2], al[cur][mi][3],
                             bh[cur][ni][0], bh[cur][ni][1]);
                }
        }
#undef LOADF

#pragma unroll
        for (int mi = 0; mi < 2; mi++) {
            int r0 = m0 + mBase + mi * 16 + grp;
            int r1 = r0 + 8;
#pragma unroll
            for (int ni = 0; ni < 4; ni++) {
                int col = n0 + nBase + ni * 8 + tig * 2;
                if (r0 < Mvalid)
                    *(float2*)(Y + (size_t)r0 * NPIX_ + col) = make_float2(acc[mi][ni][0], acc[mi][ni][1]);
                if (r1 < Mvalid)
                    *(float2*)(Y + (size_t)r1 * NPIX_ + col) = make_float2(acc[mi][ni][2], acc[mi][ni][3]);
            }
        }
    }
}

// ---------------- depthwise 3x3, 64-row tiles, float4, fused sumsq partials ----------------
#define TR_ 64
__global__ void dwconv_kernel(const float* __restrict__ in,
                              const float* __restrict__ wgt,
                              float* __restrict__ out,
                              float* __restrict__ ss) {
    __shared__ float s[TR_ + 2][HW_];
    __shared__ float red[8];
    int t = threadIdx.x;
    int ch = blockIdx.y, b = blockIdx.z;
    int y0 = blockIdx.x * TR_;
    const float* src = in + ((size_t)b * C3_ + ch) * NPIX_;
    float* dst = out + ((size_t)b * C3_ + ch) * NPIX_;
    float kw[9];
#pragma unroll
    for (int i = 0; i < 9; i++) kw[i] = wgt[ch * 9 + i];

    for (int i4 = t; i4 < (TR_ + 2) * 32; i4 += 256) {
        int r = i4 >> 5, c4 = i4 & 31;
        int y = y0 - 1 + r;
        float4 v = make_float4(0.f, 0.f, 0.f, 0.f);
        if (y >= 0 && y < HW_) v = *(const float4*)(src + y * HW_ + c4 * 4);
        *(float4*)(&s[r][c4 * 4]) = v;
    }
    __syncthreads();

    float ssum = 0.f;
    for (int p4 = t; p4 < TR_ * 32; p4 += 256) {
        int r = p4 >> 5, c4 = p4 & 31;
        int col = c4 * 4;
        float o[4];
#pragma unroll
        for (int px = 0; px < 4; px++) {
            int cc = col + px;
            float acc = 0.f;
            bool cl = cc > 0, cr = cc < HW_ - 1;
#pragma unroll
            for (int dy = 0; dy < 3; dy++) {
                const float* row = s[r + dy];
                if (cl) acc += row[cc - 1] * kw[dy * 3 + 0];
                acc += row[cc] * kw[dy * 3 + 1];
                if (cr) acc += row[cc + 1] * kw[dy * 3 + 2];
            }
            o[px] = acc;
            ssum += acc * acc;
        }
        *(float4*)(dst + (y0 + r) * HW_ + col) = make_float4(o[0], o[1], o[2], o[3]);
    }

    if (ch < 2 * C_) {
#pragma unroll
        for (int o = 16; o > 0; o >>= 1) ssum += __shfl_down_sync(0xffffffffu, ssum, o);
        if ((t & 31) == 0) red[t >> 5] = ssum;
        __syncthreads();
        if (t == 0) {
            float tot = 0.f;
#pragma unroll
            for (int i = 0; i < 8; i++) tot += red[i];
            ss[(b * 2 * C_ + ch) * 2 + blockIdx.x] = tot;
        }
    }
}

// ---------------- Gram partials: 3x3 register tiling, 4 groups/block ----------------
__global__ void gram_partial(const float* __restrict__ qkv2, float* __restrict__ gpart) {
    extern __shared__ float gsm[];
    int t = threadIdx.x;
    int grp = t >> 6, lt = t & 63;
    int h = blockIdx.y, b = blockIdx.z;
    int gi = blockIdx.x * 4 + grp;
    float* qs = gsm + grp * (2 * HD_ * GROW_);
    float* ks = qs + HD_ * GROW_;
    const float* qb = qkv2 + ((size_t)b * C3_ + h * HD_) * NPIX_;
    const float* kb = qkv2 + ((size_t)b * C3_ + C_ + h * HD_) * NPIX_;
    int i = lt >> 3, j = lt & 7;

    float acc[3][3];
#pragma unroll
    for (int r = 0; r < 3; r++)
#pragma unroll
        for (int s2 = 0; s2 < 3; s2++) acc[r][s2] = 0.f;

    for (int chk = 0; chk < 8; chk++) {
        int n0 = gi * 1024 + chk * 128;
        __syncthreads();
        for (int idx = lt; idx < HD_ * 32; idx += 64) {
            int c = idx >> 5, v4 = idx & 31;
            *(float4*)(qs + c * GROW_ + v4 * 4) = *(const float4*)(qb + (size_t)c * NPIX_ + n0 + v4 * 4);
            *(float4*)(ks + c * GROW_ + v4 * 4) = *(const float4*)(kb + (size_t)c * NPIX_ + n0 + v4 * 4);
        }
        __syncthreads();
        const float* q0 = qs + (3 * i) * GROW_;
        const float* k0 = ks + (3 * j) * GROW_;
#pragma unroll 4
        for (int nn = 0; nn < 128; nn += 4) {
            float4 qv[3], kv[3];
#pragma unroll
            for (int r = 0; r < 3; r++) {
                qv[r] = *(const float4*)(q0 + r * GROW_ + nn);
                kv[r] = *(const float4*)(k0 + r * GROW_ + nn);
            }
#pragma unroll
            for (int r = 0; r < 3; r++)
#pragma unroll
                for (int s2 = 0; s2 < 3; s2++)
                    acc[r][s2] += qv[r].x * kv[s2].x + qv[r].y * kv[s2].y
                                + qv[r].z * kv[s2].z + qv[r].w * kv[s2].w;
        }
    }

    float* outp = gpart + (((size_t)(b * HEADS_ + h)) * GSLICES_ + gi) * (HD_ * HD_);
#pragma unroll
    for (int r = 0; r < 3; r++)
#pragma unroll
        for (int s2 = 0; s2 < 3; s2++)
            outp[(3 * i + r) * HD_ + 3 * j + s2] = acc[r][s2];
}

// ---------------- reduce partials + rnorm scale + softmax ----------------
__global__ void softmax_kernel(const float* __restrict__ gpart,
                               const float* __restrict__ ss,
                               float* __restrict__ attn) {
    int h = blockIdx.x, b = blockIdx.y;
    int t = threadIdx.x;
    int c = t / HD_, d = t - c * HD_;
    __shared__ float rq[HD_], rk[HD_];
    __shared__ float S[HD_][HD_ + 1];
    if (t < HD_) {
        const float* p = ss + (b * 2 * C_ + h * HD_ + t) * 2;
        rq[t] = 1.f / fmaxf(sqrtf(p[0] + p[1]), 1e-12f);
    } else if (t < 2 * HD_) {
        int d2 = t - HD_;
        const float* p = ss + (b * 2 * C_ + C_ + h * HD_ + d2) * 2;
        rk[d2] = 1.f / fmaxf(sqrtf(p[0] + p[1]), 1e-12f);
    }
    const float* gp = gpart + ((size_t)(b * HEADS_ + h)) * GSLICES_ * (HD_ * HD_) + t;
    float acc = 0.f;
#pragma unroll
    for (int sidx = 0; sidx < GSLICES_; sidx++) acc += gp[(size_t)sidx * (HD_ * HD_)];
    __syncthreads();
    S[c][d] = acc * rq[c] * rk[d] * 0.20412414523193154f;
    __syncthreads();
    if (d == 0) {
        float m = -1e30f;
        for (int jj = 0; jj < HD_; jj++) m = fmaxf(m, S[c][jj]);
        float sse = 0.f;
        for (int jj = 0; jj < HD_; jj++) { float e = expf(S[c][jj] - m); S[c][jj] = e; sse += e; }
        float inv = 1.f / sse;
        for (int jj = 0; jj < HD_; jj++) S[c][jj] *= inv;
    }
    __syncthreads();
    attn[(((size_t)b * HEADS_ + h) * HD_ + c) * HD_ + d] = S[c][d];
}

// ---------------- out = (attn @ v) * gate -> transposed split-bf16 (coalesced) ----------------
__global__ void av_kernel(const float* __restrict__ qkv2,
                          const float* __restrict__ attn,
                          const float* __restrict__ gates,
                          uint32_t* __restrict__ ot_hi,
                          uint32_t* __restrict__ ot_lo) {
    int n0 = blockIdx.x * 256;
    int n = n0 + threadIdx.x;
    int h = blockIdx.y, b = blockIdx.z;
    __shared__ float A[HD_][HD_];
    __shared__ uint32_t sh[256][13];
    __shared__ uint32_t sl[256][13];
    const float* ab = attn + ((size_t)b * HEADS_ + h) * HD_ * HD_;
    for (int i = threadIdx.x; i < HD_ * HD_; i += 256) A[i / HD_][i % HD_] = ab[i];
    __syncthreads();
    const float* v = qkv2 + ((size_t)b * C3_ + 2 * C_ + h * HD_) * NPIX_ + n;
    float acc[HD_];
#pragma unroll
    for (int c = 0; c < HD_; c++) acc[c] = 0.f;
#pragma unroll
    for (int d = 0; d < HD_; d++) {
        float vv = v[(size_t)d * NPIX_];
#pragma unroll
        for (int c = 0; c < HD_; c++) acc[c] += A[c][d] * vv;
    }
    float g = gates[((size_t)b * HEADS_ + h) * NPIX_ + n];
#pragma unroll
    for (int c2 = 0; c2 < 12; c2++) {
        float v0 = acc[2 * c2] * g, v1 = acc[2 * c2 + 1] * g;
        __nv_bfloat16 h0 = __float2bfloat16(v0), h1 = __float2bfloat16(v1);
        __nv_bfloat162 hp; hp.x = h0; hp.y = h1;
        sh[threadIdx.x][c2] = *(uint32_t*)&hp;
        __nv_bfloat162 lp;
        lp.x = __float2bfloat16(v0 - __bfloat162float(h0));
        lp.y = __float2bfloat16(v1 - __bfloat162float(h1));
        sl[threadIdx.x][c2] = *(uint32_t*)&lp;
    }
    __syncthreads();
    for (int i = threadIdx.x; i < 256 * 12; i += 256) {
        int p = i / 12, c2 = i - p * 12;
        size_t o = ((size_t)b * NPIX_ + n0 + p) * 96 + h * 12 + c2;
        ot_hi[o] = sh[p][c2];
        ot_lo[o] = sl[p][c2];
    }
}

// ---------------- launch ----------------
extern "C" void kernel_launch(void* const* d_in, const int* in_sizes, int n_in,
                              void* d_out, int out_size) {
    const float* x       = (const float*)d_in[0];
    const float* qkv_w   = (const float*)d_in[1];
    const float* dw_w    = (const float*)d_in[2];
    const float* proj_w  = (const float*)d_in[3];
    const float* rw_main = (const float*)d_in[4];
    const float* rw_aux  = (const float*)d_in[5];
    const int*   task_id = (const int*)d_in[6];
    float* out = (float*)d_out;

    float *qkv, *qkv2, *gates, *ss, *gpart, *attn;
    __nv_bfloat16 *xt_hi, *xt_lo, *ot_hi, *ot_lo, *wq_hi, *wq_lo, *wp_hi, *wp_lo;
    cudaGetSymbolAddress((void**)&qkv,   g_qkv);
    cudaGetSymbolAddress((void**)&qkv2,  g_qkv2);
    cudaGetSymbolAddress((void**)&gates, g_gates);
    cudaGetSymbolAddress((void**)&ss,    g_ss);
    cudaGetSymbolAddress((void**)&gpart, g_gram_part);
    cudaGetSymbolAddress((void**)&attn,  g_attn);
    cudaGetSymbolAddress((void**)&xt_hi, g_xt_hi);
    cudaGetSymbolAddress((void**)&xt_lo, g_xt_lo);
    cudaGetSymbolAddress((void**)&ot_hi, g_ot_hi);
    cudaGetSymbolAddress((void**)&ot_lo, g_ot_lo);
    cudaGetSymbolAddress((void**)&wq_hi, g_wq_hi);
    cudaGetSymbolAddress((void**)&wq_lo, g_wq_lo);
    cudaGetSymbolAddress((void**)&wp_hi, g_wp_hi);
    cudaGetSymbolAddress((void**)&wp_lo, g_wp_lo);

    cudaFuncSetAttribute(gemm_mma, cudaFuncAttributeMaxDynamicSharedMemorySize, SM_GEMM_);
    cudaFuncSetAttribute(gram_partial, cudaFuncAttributeMaxDynamicSharedMemorySize, GSM_GRAM_);

    split_w_kernel<<<(C3_ * K_ + 255) / 256, 256>>>(qkv_w, wq_hi, wq_lo, C3_ * K_);
    split_w_kernel<<<(C_ * K_ + 255) / 256, 256>>>(proj_w, wp_hi, wp_lo, C_ * K_);
    fused_tr_router<<<dim3(NPIX_ / 32, B_), 256>>>(x, rw_main, rw_aux, task_id, xt_hi, xt_lo, gates);
    // qkv = W_qkv @ x : 576 rows = exactly 9 m-tiles
    gemm_mma<<<dim3(NPIX_ / BN_, 1, B_), 256, SM_GEMM_>>>(wq_hi, wq_lo, xt_hi, xt_lo, qkv, C3_, 9);
    dwconv_kernel<<<dim3(HW_ / TR_, C3_, B_), 256>>>(qkv, dw_w, qkv2, ss);
    gram_partial<<<dim3(4, HEADS_, B_), 256, GSM_GRAM_>>>(qkv2, gpart);
    softmax_kernel<<<dim3(HEADS_, B_), 576>>>(gpart, ss, attn);
    av_kernel<<<dim3(NPIX_ / 256, HEADS_, B_), 256>>>(qkv2, attn, gates, (uint32_t*)ot_hi, (uint32_t*)ot_lo);
    // out = W_proj @ obuf : 192 rows = exactly 3 m-tiles
    gemm_mma<<<dim3(NPIX_ / BN_, 1, B_), 256, SM_GEMM_>>>(wp_hi, wp_lo, ot_hi, ot_lo, out, C_, 3);
}